// round 15
// baseline (speedup 1.0000x reference)
#include <cuda_runtime.h>
#include <cuda_fp16.h>
#include <math.h>
#include <stdint.h>

#define BB 32
#define LL 1024
#define MN 512
#define SD 256
#define VD 64
#define D3 192
#define DM 256
#define NH 8
#define DK 32

// ---------------- scratch (device globals; no allocation allowed) ----------------
__device__ float g_pos_sum[MN * D3];
__device__ float g_gamma[BB * MN * DM];
__device__ __half g_xmh[BB * MN * D3];
__device__ __half g_peh[BB * MN * D3];
__device__ __half g_Qh[BB * LL * DM];
__device__ __half g_Kh[BB * MN * DM];
__device__ __half g_Vh[BB * MN * DM];
__device__ __half g_attnh[BB * LL * DM];
__device__ __half g_Wkh[DM * D3];
__device__ __half g_Wvh[DM * D3];
__device__ __half g_Wfh[DM * DM];
__device__ uint2 g_wf[7 * 24 * 4 * 32];   // conv weights, fragment-major coalesced

// ================= helpers =========================================================
__device__ __forceinline__ uint32_t h2u(float a, float b) {
    __half2 h = __floats2half2_rn(a, b);
    return *(uint32_t*)&h;
}
__device__ __forceinline__ float2 u2f2(uint32_t u) {
    return __half22float2(*(__half2*)&u);
}
__device__ __forceinline__ uint32_t f22h2(float lo, float hi) {
    uint32_t r;
    asm("cvt.rn.f16x2.f32 %0, %1, %2;" : "=r"(r) : "f"(hi), "f"(lo));
    return r;
}
__device__ __forceinline__ uint32_t ex2h2(uint32_t x) {
    uint32_t r;
    asm("ex2.approx.f16x2 %0, %1;" : "=r"(r) : "r"(x));
    return r;
}
__device__ __forceinline__ void mma_f16(float* c, uint4 a, uint2 b) {
    asm("mma.sync.aligned.m16n8k16.row.col.f32.f16.f16.f32 "
        "{%0,%1,%2,%3}, {%4,%5,%6,%7}, {%8,%9}, {%0,%1,%2,%3};"
        : "+f"(c[0]), "+f"(c[1]), "+f"(c[2]), "+f"(c[3])
        : "r"(a.x), "r"(a.y), "r"(a.z), "r"(a.w), "r"(b.x), "r"(b.y));
}
__device__ __forceinline__ void ldmx4(uint4& v, uint32_t addr) {
    asm volatile("ldmatrix.sync.aligned.m8n8.x4.shared.b16 {%0,%1,%2,%3}, [%4];"
        : "=r"(v.x), "=r"(v.y), "=r"(v.z), "=r"(v.w) : "r"(addr));
}
__device__ __forceinline__ uint32_t smem_u32(const void* p) {
    uint32_t a;
    asm("{ .reg .u64 t; cvta.to.shared.u64 t, %1; cvt.u32.u64 %0, t; }" : "=r"(a) : "l"(p));
    return a;
}

// lane-constant fragment offsets (A m16k16 / B 2x(n8k16) ldmatrix.x4 maps)
#define LANE_FRAG_OFFS(lane)                                   \
    int rowA = (lane) & 15;                                    \
    int kA = ((lane) >> 4) * 16;          /* bytes */          \
    int rowB = ((lane) & 7) + (((lane) >> 4) << 3);            \
    int kB = ((lane) & 8) * 2;            /* bytes */

// GEMM smem: half tiles, 128 rows x 32 halves, padded to 40 halves (80 B/row)
#define GS_AS 20
#define GS_TILE (128 * GS_AS)
#define GSM_BYTES (4 * GS_TILE * 4)   // 40960 B

// ---------------- float-input GEMM (Q / Gamma; side stream) ------------------------
__global__ void __launch_bounds__(256, 2) mgemm_kernel(
    const float* __restrict__ A, const float* __restrict__ W,
    float* __restrict__ Cf, __half* __restrict__ Ch,
    int Kd, int sigmoidFlag, float outScale) {
    extern __shared__ uint32_t gsm[];
    uint32_t sb = smem_u32(gsm);
    int tid = threadIdx.x;
    int lane = tid & 31, wid = tid >> 5;
    int mw = wid & 1, nw = wid >> 1;
    int qd = lane >> 2, pd = lane & 3;
    LANE_FRAG_OFFS(lane);
    int m0 = blockIdx.y * 128;
    int n0b = blockIdx.x * 128;
    int NC = Kd >> 5;

    float acc[4][4][4];
    #pragma unroll
    for (int t = 0; t < 4; t++)
        #pragma unroll
        for (int u = 0; u < 4; u++)
            #pragma unroll
            for (int j = 0; j < 4; j++) acc[t][u][j] = 0.f;

    {
        uint32_t* Ad = gsm;
        uint32_t* Bd = gsm + 2 * GS_TILE;
        #pragma unroll
        for (int i = 0; i < 4; i++) {
            int g = tid + i * 256;
            int row = g >> 3, q = g & 7;
            float4 va = *(const float4*)&A[(size_t)(m0 + row) * Kd + q * 4];
            float4 vb = *(const float4*)&W[(size_t)(n0b + row) * Kd + q * 4];
            *(uint2*)&Ad[row * GS_AS + q * 2] = make_uint2(h2u(va.x, va.y), h2u(va.z, va.w));
            *(uint2*)&Bd[row * GS_AS + q * 2] = make_uint2(h2u(vb.x, vb.y), h2u(vb.z, vb.w));
        }
    }
    __syncthreads();

    for (int c = 0; c < NC; c++) {
        uint32_t Ab = sb + ((c & 1) ? GS_TILE * 4 : 0);
        uint32_t Bb = sb + 2 * GS_TILE * 4 + ((c & 1) ? GS_TILE * 4 : 0);

        uint2 pah[4], pbh[4];
        if (c + 1 < NC) {
            int kk = (c + 1) * 32;
            #pragma unroll
            for (int i = 0; i < 4; i++) {
                int g = tid + i * 256;
                int row = g >> 3, q = g & 7;
                float4 va = *(const float4*)&A[(size_t)(m0 + row) * Kd + kk + q * 4];
                float4 vb = *(const float4*)&W[(size_t)(n0b + row) * Kd + kk + q * 4];
                pah[i] = make_uint2(h2u(va.x, va.y), h2u(va.z, va.w));
                pbh[i] = make_uint2(h2u(vb.x, vb.y), h2u(vb.z, vb.w));
            }
        }

        #pragma unroll
        for (int ks = 0; ks < 2; ks++) {
            uint4 av[4];
            uint2 bv[4];
            #pragma unroll
            for (int t = 0; t < 4; t++)
                ldmx4(av[t], Ab + (mw * 64 + t * 16 + rowA) * 80 + ks * 32 + kA);
            uint4 b01, b23;
            ldmx4(b01, Bb + (nw * 32 + rowB) * 80 + ks * 32 + kB);
            ldmx4(b23, Bb + (nw * 32 + 16 + rowB) * 80 + ks * 32 + kB);
            bv[0] = make_uint2(b01.x, b01.y); bv[1] = make_uint2(b01.z, b01.w);
            bv[2] = make_uint2(b23.x, b23.y); bv[3] = make_uint2(b23.z, b23.w);
            #pragma unroll
            for (int t = 0; t < 4; t++)
                #pragma unroll
                for (int u = 0; u < 4; u++)
                    mma_f16(acc[t][u], av[t], bv[u]);
        }

        if (c + 1 < NC) {
            __syncthreads();
            uint32_t* Ad = gsm + (((c + 1) & 1) ? GS_TILE : 0);
            uint32_t* Bd = gsm + 2 * GS_TILE + (((c + 1) & 1) ? GS_TILE : 0);
            #pragma unroll
            for (int i = 0; i < 4; i++) {
                int g = tid + i * 256;
                int row = g >> 3, q = g & 7;
                *(uint2*)&Ad[row * GS_AS + q * 2] = pah[i];
                *(uint2*)&Bd[row * GS_AS + q * 2] = pbh[i];
            }
            __syncthreads();
        }
    }

    #pragma unroll
    for (int t = 0; t < 4; t++) {
        int r0 = m0 + mw * 64 + t * 16 + qd;
        #pragma unroll
        for (int u = 0; u < 4; u++) {
            int col = n0b + nw * 32 + u * 8 + pd * 2;
            float v0 = acc[t][u][0], v1 = acc[t][u][1];
            float v2 = acc[t][u][2], v3 = acc[t][u][3];
            if (Ch) {
                *(uint32_t*)&Ch[(size_t)r0 * DM + col] = h2u(v0 * outScale, v1 * outScale);
                *(uint32_t*)&Ch[(size_t)(r0 + 8) * DM + col] = h2u(v2 * outScale, v3 * outScale);
            } else {
                if (sigmoidFlag) {
                    v0 = 1.f / (1.f + __expf(-v0));
                    v1 = 1.f / (1.f + __expf(-v1));
                    v2 = 1.f / (1.f + __expf(-v2));
                    v3 = 1.f / (1.f + __expf(-v3));
                }
                *(float2*)&Cf[(size_t)r0 * DM + col]       = make_float2(v0, v1);
                *(float2*)&Cf[(size_t)(r0 + 8) * DM + col] = make_float2(v2, v3);
            }
        }
    }
}

// ---------------- K+V fused GEMM: half A (pe), half W, ldmatrix fragments ----------
__global__ void __launch_bounds__(256, 2) kvgemm_kernel() {
    extern __shared__ uint32_t gsm[];
    uint32_t sb = smem_u32(gsm);
    int tid = threadIdx.x;
    int lane = tid & 31, wid = tid >> 5;
    int mw = wid & 1, nw = wid >> 1;
    int qd = lane >> 2, pd = lane & 3;
    LANE_FRAG_OFFS(lane);
    int bx = blockIdx.x;
    int n0b = (bx & 1) * 128;
    const __half* A = g_peh;
    const __half* W = (bx >> 1) ? g_Wvh : g_Wkh;
    __half* C = (bx >> 1) ? g_Vh : g_Kh;
    int m0 = blockIdx.y * 128;
    const int NC = 6;

    float acc[4][4][4];
    #pragma unroll
    for (int t = 0; t < 4; t++)
        #pragma unroll
        for (int u = 0; u < 4; u++)
            #pragma unroll
            for (int j = 0; j < 4; j++) acc[t][u][j] = 0.f;

    {
        uint32_t* Ad = gsm;
        uint32_t* Bd = gsm + 2 * GS_TILE;
        #pragma unroll
        for (int i = 0; i < 2; i++) {
            int g = tid + i * 256;
            int row = g >> 2, q = g & 3;
            *(uint4*)&Ad[row * GS_AS + q * 4] =
                *(const uint4*)&A[(size_t)(m0 + row) * D3 + q * 8];
            *(uint4*)&Bd[row * GS_AS + q * 4] =
                *(const uint4*)&W[(size_t)(n0b + row) * D3 + q * 8];
        }
    }
    __syncthreads();

    for (int c = 0; c < NC; c++) {
        uint32_t Ab = sb + ((c & 1) ? GS_TILE * 4 : 0);
        uint32_t Bb = sb + 2 * GS_TILE * 4 + ((c & 1) ? GS_TILE * 4 : 0);

        uint4 pah[2], pbh[2];
        if (c + 1 < NC) {
            int kk = (c + 1) * 32;
            #pragma unroll
            for (int i = 0; i < 2; i++) {
                int g = tid + i * 256;
                int row = g >> 2, q = g & 3;
                pah[i] = *(const uint4*)&A[(size_t)(m0 + row) * D3 + kk + q * 8];
                pbh[i] = *(const uint4*)&W[(size_t)(n0b + row) * D3 + kk + q * 8];
            }
        }

        #pragma unroll
        for (int ks = 0; ks < 2; ks++) {
            uint4 av[4];
            uint2 bv[4];
            #pragma unroll
            for (int t = 0; t < 4; t++)
                ldmx4(av[t], Ab + (mw * 64 + t * 16 + rowA) * 80 + ks * 32 + kA);
            uint4 b01, b23;
            ldmx4(b01, Bb + (nw * 32 + rowB) * 80 + ks * 32 + kB);
            ldmx4(b23, Bb + (nw * 32 + 16 + rowB) * 80 + ks * 32 + kB);
            bv[0] = make_uint2(b01.x, b01.y); bv[1] = make_uint2(b01.z, b01.w);
            bv[2] = make_uint2(b23.x, b23.y); bv[3] = make_uint2(b23.z, b23.w);
            #pragma unroll
            for (int t = 0; t < 4; t++)
                #pragma unroll
                for (int u = 0; u < 4; u++)
                    mma_f16(acc[t][u], av[t], bv[u]);
        }

        if (c + 1 < NC) {
            __syncthreads();
            uint32_t* Ad = gsm + (((c + 1) & 1) ? GS_TILE : 0);
            uint32_t* Bd = gsm + 2 * GS_TILE + (((c + 1) & 1) ? GS_TILE : 0);
            #pragma unroll
            for (int i = 0; i < 2; i++) {
                int g = tid + i * 256;
                int row = g >> 2, q = g & 3;
                *(uint4*)&Ad[row * GS_AS + q * 4] = pah[i];
                *(uint4*)&Bd[row * GS_AS + q * 4] = pbh[i];
            }
            __syncthreads();
        }
    }

    #pragma unroll
    for (int t = 0; t < 4; t++) {
        int r0 = m0 + mw * 64 + t * 16 + qd;
        #pragma unroll
        for (int u = 0; u < 4; u++) {
            int col = n0b + nw * 32 + u * 8 + pd * 2;
            *(uint32_t*)&C[(size_t)r0 * DM + col] = h2u(acc[t][u][0], acc[t][u][1]);
            *(uint32_t*)&C[(size_t)(r0 + 8) * DM + col] = h2u(acc[t][u][2], acc[t][u][3]);
        }
    }
}

// ---------------- fused prep: conv wf + Wk/Wv/Wf halves + pos_sum ------------------
__global__ void prep_kernel(const float* __restrict__ w3, const float* __restrict__ w5,
                            const float* __restrict__ w7, const float* __restrict__ Wk,
                            const float* __restrict__ Wv, const float* __restrict__ Wf,
                            const float* __restrict__ emb) {
    int bid = blockIdx.x;
    int tid = threadIdx.x;
    if (bid < 84) {                        // conv weights fragment-major: 21504 uint2
        int idx = bid * 256 + tid;
        if (idx < 21504) {
            int lane = idx & 31;
            int ks = (idx >> 5) & 3;
            int rem = idx >> 7;            // tp*24 + ct
            int ct = rem % 24;
            int tp = rem / 24;
            int qd = lane >> 2, pd = lane & 3;
            int c = ct * 8 + qd;
            int kw0 = ks * 8 + pd;
            float v[4];
            #pragma unroll
            for (int e = 0; e < 4; e++) {
                int i = (kw0 + (e >> 1) * 4) * 2 + (e & 1);
                float val = 0.f;
                if (c < 64)       { if (tp >= 2 && tp <= 4) val = w3[(c * 64 + i) * 3 + (tp - 2)]; }
                else if (c < 128) { int cc = c - 64; if (tp >= 1 && tp <= 5) val = w5[(cc * 64 + i) * 5 + (tp - 1)]; }
                else              { int cc = c - 128; val = w7[(cc * 64 + i) * 7 + tp]; }
                v[e] = val;
            }
            g_wf[idx] = make_uint2(h2u(v[0], v[1]), h2u(v[2], v[3]));
        }
    } else if (bid < 84 + 640) {           // Wk/Wv/Wf: 163840 halves
        int idx = (bid - 84) * 256 + tid;
        const int NK = DM * D3;
        if (idx < NK) g_Wkh[idx] = __float2half_rn(Wk[idx]);
        else if (idx < 2 * NK) g_Wvh[idx - NK] = __float2half_rn(Wv[idx - NK]);
        else if (idx < 2 * NK + DM * DM) g_Wfh[idx - 2 * NK] = __float2half_rn(Wf[idx - 2 * NK]);
    } else {                               // pos_sum: 512 rows x 192
        int j = bid - (84 + 640);
        int d = tid;
        if (d < D3) {
            float acc = 0.f;
            #pragma unroll
            for (int delta = -29; delta <= 29; delta++) {
                int i = j - delta;
                if (i >= 0 && i < MN) acc += emb[(delta + 30) * D3 + d];
            }
            int cpos = j - 29;
            if (cpos > 0) acc += (float)cpos * emb[60 * D3 + d];
            int cneg = 482 - j;
            if (cneg > 0) acc += (float)cneg * emb[0 * D3 + d];
            g_pos_sum[j * D3 + d] = acc;
        }
    }
}

// ---------------- multi-scale conv: channel-split, coalesced weight frags ----------
#define CXR2 38
#define CXS 36
#define CONV_SMEM (CXR2 * CXS * 4)   // 5472 B

__device__ __forceinline__ constexpr int conv_abase(int tp) {
    return (tp >= 2 && tp <= 4) ? 0 : ((tp == 1 || tp == 5) ? 64 : 128);
}

__global__ void __launch_bounds__(128) conv_kernel(
    const float* __restrict__ xv, const float* __restrict__ b3,
    const float* __restrict__ b5, const float* __restrict__ b7) {
    extern __shared__ uint32_t csm[];
    uint32_t* xvs = csm;
    uint32_t xb = smem_u32(csm);
    int blk = blockIdx.x;              // ((b*16 + sblk) << 1) | chalf
    int ch = blk & 1;
    int sblk = (blk >> 1) & 15;
    int b = blk >> 5;
    int s0 = sblk * 32;
    int cbase = ch * 96;
    int tid = threadIdx.x;
    int lane = tid & 31, nw = tid >> 5;
    int qd = lane >> 2, pd = lane & 3;
    LANE_FRAG_OFFS(lane);
    int ct0 = ch * 12 + nw * 3;        // this warp's first 8-channel tile

    for (int g = tid; g < CXR2 * 16; g += 128) {
        int row = g >> 4, c4 = g & 15;
        int s = s0 - 3 + row;
        float4 v = make_float4(0.f, 0.f, 0.f, 0.f);
        if (s >= 0 && s < MN) v = *(const float4*)&xv[((size_t)b * MN + s) * VD + c4 * 4];
        *(uint2*)&xvs[row * CXS + c4 * 2] = make_uint2(h2u(v.x, v.y), h2u(v.z, v.w));
    }
    __syncthreads();

    float acc[2][3][4];
    #pragma unroll
    for (int t = 0; t < 2; t++)
        #pragma unroll
        for (int u = 0; u < 3; u++)
            #pragma unroll
            for (int j = 0; j < 4; j++) acc[t][u][j] = 0.f;

    uint2 bvb[2][3];
    {
        const int ab0 = conv_abase(0);
        #pragma unroll
        for (int u = 0; u < 3; u++) {
            if ((ct0 + u) * 8 >= ab0)
                bvb[0][u] = __ldg(&g_wf[(((0 * 24 + ct0 + u) * 4 + 0) << 5) + lane]);
        }
    }

    #pragma unroll
    for (int step = 0; step < 28; step++) {
        const int tp = step >> 2, ks = step & 3;
        const int abase = conv_abase(tp);

        if (step + 1 < 28) {
            const int tp2 = (step + 1) >> 2, ks2 = (step + 1) & 3;
            const int ab2 = conv_abase(tp2);
            #pragma unroll
            for (int u = 0; u < 3; u++) {
                if ((ct0 + u) * 8 >= ab2)
                    bvb[(step + 1) & 1][u] =
                        __ldg(&g_wf[(((tp2 * 24 + ct0 + u) * 4 + ks2) << 5) + lane]);
            }
        }

        uint4 av[2];
        #pragma unroll
        for (int t = 0; t < 2; t++)
            ldmx4(av[t], xb + (t * 16 + rowA + tp) * 144 + ks * 32 + kA);
        #pragma unroll
        for (int u = 0; u < 3; u++) {
            if ((ct0 + u) * 8 >= abase) {
                #pragma unroll
                for (int t = 0; t < 2; t++)
                    mma_f16(acc[t][u], av[t], bvb[step & 1][u]);
            }
        }
    }

    #pragma unroll
    for (int t = 0; t < 2; t++) {
        int s = s0 + t * 16 + qd;
        #pragma unroll
        for (int u = 0; u < 3; u++) {
            int col = cbase + nw * 24 + u * 8 + pd * 2;
            float bb0 = col < 64 ? b3[col] : (col < 128 ? b5[col - 64] : b7[col - 128]);
            int c1 = col + 1;
            float bb1 = c1 < 64 ? b3[c1] : (c1 < 128 ? b5[c1 - 64] : b7[c1 - 128]);
            *(uint32_t*)&g_xmh[((size_t)b * MN + s) * D3 + col] =
                h2u(acc[t][u][0] + bb0, acc[t][u][1] + bb1);
            *(uint32_t*)&g_xmh[((size_t)b * MN + s + 8) * D3 + col] =
                h2u(acc[t][u][2] + bb0, acc[t][u][3] + bb1);
        }
    }
}

// ---------------- rel-pos encoding: half2-vectorized -------------------------------
__global__ void pe_kernel(const float* __restrict__ emb,
                          const float* __restrict__ dww, const float* __restrict__ dwb) {
    int idx = blockIdx.x * 256 + threadIdx.x;   // half2 index; total BB*MN*96
    int d2 = idx % 96;
    int r = idx / 96;
    int j = r & (MN - 1);
    int d = d2 * 2;
    const uint32_t* xm2 = (const uint32_t*)g_xmh;
    uint32_t* pe2 = (uint32_t*)g_peh;
    float2 xc = u2f2(xm2[idx]);
    float fC0 = xc.x + emb[30 * D3 + d];
    float fC1 = xc.y + emb[30 * D3 + d + 1];
    float fL0 = 0.f, fL1 = 0.f, fR0 = 0.f, fR1 = 0.f;
    if (j > 0) {
        float2 xl = u2f2(xm2[idx - 96]);
        fL0 = xl.x + emb[29 * D3 + d];
        fL1 = xl.y + emb[29 * D3 + d + 1];
    }
    if (j < MN - 1) {
        float2 xr = u2f2(xm2[idx + 96]);
        fR0 = xr.x + emb[31 * D3 + d];
        fR1 = xr.y + emb[31 * D3 + d + 1];
    }
    float dg0 = fL0 * dww[d * 3 + 0] + fC0 * dww[d * 3 + 1] + fR0 * dww[d * 3 + 2] + dwb[d];
    float dg1 = fL1 * dww[d * 3 + 3] + fC1 * dww[d * 3 + 4] + fR1 * dww[d * 3 + 5] + dwb[d + 1];
    float o0 = xc.x + (g_pos_sum[j * D3 + d] - fC0 + dg0) * (1.0f / (float)MN);
    float o1 = xc.y + (g_pos_sum[j * D3 + d + 1] - fC1 + dg1) * (1.0f / (float)MN);
    pe2[idx] = h2u(o0, o1);
}

// ---------------- attention: pipelined s-loop, f16x2 exp ---------------------------
#define AK_STRIDE 20
#define AV_STRIDE 260
#define ATT_SMEM ((MN * AK_STRIDE + DK * AV_STRIDE) * 4)   // 74240 B

__global__ void __launch_bounds__(256, 2) attn_kernel() {
    extern __shared__ uint32_t ash[];
    uint32_t* Ks = ash;
    uint32_t* VT = ash + MN * AK_STRIDE;
    uint32_t Kb = smem_u32(ash);
    uint32_t Vb = Kb + MN * AK_STRIDE * 4;
    int blk = blockIdx.x;
    int qblk = blk & 3;
    int h = (blk >> 2) & 7;
    int b = blk >> 5;
    int tid = threadIdx.x;
    int lane = tid & 31, wid = tid >> 5;
    int qd = lane >> 2, pd = lane & 3;
    LANE_FRAG_OFFS(lane);
    (void)rowA; (void)kA;

    const __half* Kg = g_Kh + (size_t)b * MN * DM + h * DK;
    for (int i = tid; i < MN * 4; i += 256) {
        int s = i >> 2, c8 = i & 3;
        uint4 kv = *(const uint4*)&Kg[(size_t)s * DM + c8 * 8];
        *(uint4*)&Ks[s * AK_STRIDE + c8 * 4] = kv;
    }
    const __half* Vg = g_Vh + (size_t)b * MN * DM + h * DK;
    for (int g = tid; g < 1024; g += 256) {
        int spair = g >> 2, q = g & 3;
        int s = spair * 2;
        uint4 a = *(const uint4*)&Vg[(size_t)s * DM + q * 8];
        uint4 bq = *(const uint4*)&Vg[(size_t)(s + 1) * DM + q * 8];
        int d0 = q * 8;
        VT[(d0 + 0) * AV_STRIDE + spair] = (a.x & 0xFFFFu) | (bq.x << 16);
        VT[(d0 + 1) * AV_STRIDE + spair] = (a.x >> 16) | (bq.x & 0xFFFF0000u);
        VT[(d0 + 2) * AV_STRIDE + spair] = (a.y & 0xFFFFu) | (bq.y << 16);
        VT[(d0 + 3) * AV_STRIDE + spair] = (a.y >> 16) | (bq.y & 0xFFFF0000u);
        VT[(d0 + 4) * AV_STRIDE + spair] = (a.z & 0xFFFFu) | (bq.z << 16);
        VT[(d0 + 5) * AV_STRIDE + spair] = (a.z >> 16) | (bq.z & 0xFFFF0000u);
        VT[(d0 + 6) * AV_STRIDE + spair] = (a.w & 0xFFFFu) | (bq.w << 16);
        VT[(d0 + 7) * AV_STRIDE + spair] = (a.w >> 16) | (bq.w & 0xFFFF0000u);
    }
    __syncthreads();

    int m0 = qblk * 256 + wid * 32;
    const __half* Qg = g_Qh + ((size_t)b * LL + m0) * DM + h * DK;
    uint4 aq[2][2];
    #pragma unroll
    for (int t = 0; t < 2; t++)
        #pragma unroll
        for (int ks = 0; ks < 2; ks++) {
            int r = t * 16 + qd;
            int c = ks * 16 + pd * 2;
            aq[t][ks].x = *(const uint32_t*)&Qg[(size_t)r * DM + c];
            aq[t][ks].y = *(const uint32_t*)&Qg[(size_t)(r + 8) * DM + c];
            aq[t][ks].z = *(const uint32_t*)&Qg[(size_t)r * DM + c + 8];
            aq[t][ks].w = *(const uint32_t*)&Qg[(size_t)(r + 8) * DM + c + 8];
        }

    float o[2][4][4];
    #pragma unroll
    for (int t = 0; t < 2; t++)
        #pragma unroll
        for (int nv = 0; nv < 4; nv++)
            #pragma unroll
            for (int j = 0; j < 4; j++) o[t][nv][j] = 0.f;
    float rs[2][2] = {{0.f, 0.f}, {0.f, 0.f}};

    // double-buffered K fragments: preload s0 = 0
    uint2 bk[2][2][2];   // [buf][n][ks]
    {
        uint4 m;
        #pragma unroll
        for (int ks = 0; ks < 2; ks++) {
            ldmx4(m, Kb + rowB * 80 + ks * 32 + kB);
            bk[0][0][ks] = make_uint2(m.x, m.y);
            bk[0][1][ks] = make_uint2(m.z, m.w);
        }
    }

    for (int s0 = 0; s0 < MN; s0 += 16) {
        int buf = (s0 >> 4) & 1;

        // V fragments for this block (independent — issue before mma)
        uint2 bv[4];
        {
            uint4 m0v, m1v;
            ldmx4(m0v, Vb + rowB * 1040 + s0 * 2 + kB);
            ldmx4(m1v, Vb + (16 + rowB) * 1040 + s0 * 2 + kB);
            bv[0] = make_uint2(m0v.x, m0v.y); bv[1] = make_uint2(m0v.z, m0v.w);
            bv[2] = make_uint2(m1v.x, m1v.y); bv[3] = make_uint2(m1v.z, m1v.w);
        }

        // S = Q K^T
        float c[2][2][4];
        #pragma unroll
        for (int t = 0; t < 2; t++)
            #pragma unroll
            for (int n = 0; n < 2; n++) {
                #pragma unroll
                for (int j = 0; j < 4; j++) c[t][n][j] = 0.f;
                #pragma unroll
                for (int ks = 0; ks < 2; ks++)
                    mma_f16(c[t][n], aq[t][ks], bk[buf][n][ks]);
            }

        // prefetch next block's K fragments (overlaps exp below)
        if (s0 + 16 < MN) {
            uint4 m;
            #pragma unroll
            for (int ks = 0; ks < 2; ks++) {
                ldmx4(m, Kb + (s0 + 16 + rowB) * 80 + ks * 32 + kB);
                bk[buf ^ 1][0][ks] = make_uint2(m.x, m.y);
                bk[buf ^ 1][1][ks] = make_uint2(m.z, m.w);
            }
        }

        // exp in f16x2; rowsum via HADD2 then float accumulate
        uint4 ap[2];
        #pragma unroll
        for (int t = 0; t < 2; t++) {
            uint32_t p0 = ex2h2(f22h2(c[t][0][0], c[t][0][1]));
            uint32_t p1 = ex2h2(f22h2(c[t][0][2], c[t][0][3]));
            uint32_t p2 = ex2h2(f22h2(c[t][1][0], c[t][1][1]));
            uint32_t p3 = ex2h2(f22h2(c[t][1][2], c[t][1][3]));
            ap[t] = make_uint4(p0, p1, p2, p3);
            __half2 sh0 = __hadd2(*(__half2*)&p0, *(__half2*)&p2);
            __half2 sh1 = __hadd2(*(__half2*)&p1, *(__half2*)&p3);
            float2 f0 = __half22float2(sh0);
            float2 f1 = __half22float2(sh1);
            rs[t][0] += f0.x + f0.y;
            rs[t][1] += f1.x + f1.y;
        }

        // O += P V
        #pragma unroll
        for (int t = 0; t < 2; t++)
            #pragma unroll
            for (int nv = 0; nv < 4; nv++)
                mma_f16(o[t][nv], ap[t], bv[nv]);
    }

    __half* Ah = g_attnh;
    #pragma unroll
    for (int t = 0; t < 2; t++) {
        #pragma unroll
        for (int r = 0; r < 2; r++) {
            rs[t][r] += __shfl_xor_sync(0xFFFFFFFFu, rs[t][r], 1);
            rs[t][r] += __shfl_xor_sync(0xFFFFFFFFu, rs[t][r], 2);
        }
        float inv0 = 1.f / rs[t][0];
        float inv1 = 1.f / rs[t][1];
        int r0 = m0 + t * 16 + qd;
        #pragma unroll
        for (int nv = 0; nv < 4; nv++) {
            int col = h * DK + nv * 8 + pd * 2;
            *(uint32_t*)&Ah[((size_t)b * LL + r0) * DM + col] =
                h2u(o[t][nv][0] * inv0, o[t][nv][1] * inv0);
            *(uint32_t*)&Ah[((size_t)b * LL + r0 + 8) * DM + col] =
                h2u(o[t][nv][2] * inv1, o[t][nv][3] * inv1);
        }
    }
}

// ---------------- fc GEMM fused with gate + residual + LayerNorm ------------------
#define FA_TILE (64 * GS_AS)
#define FB_TILE (256 * GS_AS)
#define FSM_BYTES ((2 * FA_TILE + 2 * FB_TILE + 512) * 4)   // 53248 B

__global__ void __launch_bounds__(256, 2) fcln_kernel(
    const float* __restrict__ fb, const float* __restrict__ xs,
    const float* __restrict__ lnw, const float* __restrict__ lnb,
    float* __restrict__ out) {
    extern __shared__ uint32_t fsm[];
    uint32_t sb = smem_u32(fsm);
    float* red = (float*)(fsm + 2 * FA_TILE + 2 * FB_TILE);
    const __half* A = g_attnh;
    const __half* Wf = g_Wfh;
    int tid = threadIdx.x;
    int lane = tid & 31, wid = tid >> 5;
    int mw = wid & 1, nw = wid >> 1;
    int qd = lane >> 2, pd = lane & 3;
    LANE_FRAG_OFFS(lane);
    int row0 = blockIdx.x * 64;
    int b = row0 >> 10;
    const int NC = 8;

    float acc[2][8][4];
    #pragma unroll
    for (int t = 0; t < 2; t++)
        #pragma unroll
        for (int u = 0; u < 8; u++)
            #pragma unroll
            for (int j = 0; j < 4; j++) acc[t][u][j] = 0.f;

    {
        uint32_t* Ad = fsm;
        uint32_t* Bd = fsm + 2 * FA_TILE;
        #pragma unroll
        for (int i = 0; i < 5; i++) {
            int g = tid + i * 256;
            if (g < 256) {
                int row = g >> 2, q = g & 3;
                *(uint4*)&Ad[row * GS_AS + q * 4] =
                    *(const uint4*)&A[(size_t)(row0 + row) * DM + q * 8];
            } else {
                int j = g - 256;
                int row = j >> 2, q = j & 3;
                *(uint4*)&Bd[row * GS_AS + q * 4] =
                    *(const uint4*)&Wf[(size_t)row * DM + q * 8];
            }
        }
    }
    __syncthreads();

    for (int c = 0; c < NC; c++) {
        uint32_t Ab = sb + ((c & 1) ? FA_TILE * 4 : 0);
        uint32_t Bb = sb + 2 * FA_TILE * 4 + ((c & 1) ? FB_TILE * 4 : 0);

        uint4 pf[5];
        if (c + 1 < NC) {
            int kk = (c + 1) * 32;
            #pragma unroll
            for (int i = 0; i < 5; i++) {
                int g = tid + i * 256;
                if (g < 256) {
                    int row = g >> 2, q = g & 3;
                    pf[i] = *(const uint4*)&A[(size_t)(row0 + row) * DM + kk + q * 8];
                } else {
                    int j = g - 256;
                    int row = j >> 2, q = j & 3;
                    pf[i] = *(const uint4*)&Wf[(size_t)row * DM + kk + q * 8];
                }
            }
        }

        #pragma unroll
        for (int ks = 0; ks < 2; ks++) {
            uint4 av[2];
            uint2 bv[8];
            #pragma unroll
            for (int t = 0; t < 2; t++)
                ldmx4(av[t], Ab + (mw * 32 + t * 16 + rowA) * 80 + ks * 32 + kA);
            #pragma unroll
            for (int u2 = 0; u2 < 4; u2++) {
                uint4 m;
                ldmx4(m, Bb + (nw * 64 + u2 * 16 + rowB) * 80 + ks * 32 + kB);
                bv[u2 * 2] = make_uint2(m.x, m.y);
                bv[u2 * 2 + 1] = make_uint2(m.z, m.w);
            }
            #pragma unroll
            for (int t = 0; t < 2; t++)
                #pragma unroll
                for (int u = 0; u < 8; u++)
                    mma_f16(acc[t][u], av[t], bv[u]);
        }

        if (c + 1 < NC) {
            __syncthreads();
            uint32_t* Ad = fsm + (((c + 1) & 1) ? FA_TILE : 0);
            uint32_t* Bd = fsm + 2 * FA_TILE + (((c + 1) & 1) ? FB_TILE : 0);
            #pragma unroll
            for (int i = 0; i < 5; i++) {
                int g = tid + i * 256;
                if (g < 256) {
                    int row = g >> 2, q = g & 3;
                    *(uint4*)&Ad[row * GS_AS + q * 4] = pf[i];
                } else {
                    int j = g - 256;
                    int row = j >> 2, q = j & 3;
                    *(uint4*)&Bd[row * GS_AS + q * 4] = pf[i];
                }
            }
            __syncthreads();
        }
    }

    __syncthreads();
    #pragma unroll
    for (int t = 0; t < 2; t++) {
        #pragma unroll
        for (int hf = 0; hf < 2; hf++) {
            int lr = mw * 32 + t * 16 + qd + hf * 8;
            int r = row0 + lr;
            int l = r & 1023;
            const float* gam = g_gamma + ((size_t)b * MN + (l & (MN - 1))) * DM;
            const float* xr = xs + (size_t)r * DM;
            float s1 = 0.f, s2 = 0.f;
            #pragma unroll
            for (int u = 0; u < 8; u++) {
                int col = nw * 64 + u * 8 + pd * 2;
                int j0 = hf * 2;
                float v0 = xr[col] + gam[col] * (acc[t][u][j0] + fb[col]);
                float v1 = xr[col + 1] + gam[col + 1] * (acc[t][u][j0 + 1] + fb[col + 1]);
                acc[t][u][j0] = v0;
                acc[t][u][j0 + 1] = v1;
                s1 += v0 + v1;
                s2 += v0 * v0 + v1 * v1;
            }
            s1 += __shfl_xor_sync(0xFFFFFFFFu, s1, 1);
            s1 += __shfl_xor_sync(0xFFFFFFFFu, s1, 2);
            s2 += __shfl_xor_sync(0xFFFFFFFFu, s2, 1);
            s2 += __shfl_xor_sync(0xFFFFFFFFu, s2, 2);
            if (pd == 0) {
                red[nw * 64 + lr] = s1;
                red[256 + nw * 64 + lr] = s2;
            }
        }
    }
    __syncthreads();
    #pragma unroll
    for (int t = 0; t < 2; t++) {
        #pragma unroll
        for (int hf = 0; hf < 2; hf++) {
            int lr = mw * 32 + t * 16 + qd + hf * 8;
            int r = row0 + lr;
            float t1 = red[lr] + red[64 + lr] + red[128 + lr] + red[192 + lr];
            float t2 = red[256 + lr] + red[320 + lr] + red[384 + lr] + red[448 + lr];
            float mu = t1 * (1.f / 256.f);
            float var = t2 * (1.f / 256.f) - mu * mu;
            float rstd = rsqrtf(var + 1e-5f);
            #pragma unroll
            for (int u = 0; u < 8; u++) {
                int col = nw * 64 + u * 8 + pd * 2;
                int j0 = hf * 2;
                float v0 = (acc[t][u][j0] - mu) * rstd * lnw[col] + lnb[col];
                float v1 = (acc[t][u][j0 + 1] - mu) * rstd * lnw[col + 1] + lnb[col + 1];
                *(float2*)&out[(size_t)r * DM + col] = make_float2(v0, v1);
            }
        }
    }
}

// ---------------- launch: fork side stream FIRST (Q/Gamma independent of prep) -----
extern "C" void kernel_launch(void* const* d_in, const int* in_sizes, int n_in,
                              void* d_out, int out_size) {
    const float* x_spatial  = (const float*)d_in[0];
    const float* x_velocity = (const float*)d_in[1];
    const float* Wg    = (const float*)d_in[2];
    const float* ms_w3 = (const float*)d_in[3];
    const float* ms_b3 = (const float*)d_in[4];
    const float* ms_w5 = (const float*)d_in[5];
    const float* ms_b5 = (const float*)d_in[6];
    const float* ms_w7 = (const float*)d_in[7];
    const float* ms_b7 = (const float*)d_in[8];
    const float* rel_emb = (const float*)d_in[9];
    const float* dw_w  = (const float*)d_in[10];
    const float* dw_b  = (const float*)d_in[11];
    const float* Wq    = (const float*)d_in[12];
    const float* Wk    = (const float*)d_in[13];
    const float* Wv    = (const float*)d_in[14];
    const float* fc_w  = (const float*)d_in[15];
    const float* fc_b  = (const float*)d_in[16];
    const float* ln_w  = (const float*)d_in[17];
    const float* ln_b  = (const float*)d_in[18];
    float* out = (float*)d_out;

    float *p_gamma;
    __half *p_Qh;
    cudaGetSymbolAddress((void**)&p_gamma, g_gamma);
    cudaGetSymbolAddress((void**)&p_Qh,    g_Qh);

    cudaFuncSetAttribute(conv_kernel,   cudaFuncAttributeMaxDynamicSharedMemorySize, CONV_SMEM);
    cudaFuncSetAttribute(attn_kernel,   cudaFuncAttributeMaxDynamicSharedMemorySize, ATT_SMEM);
    cudaFuncSetAttribute(mgemm_kernel,  cudaFuncAttributeMaxDynamicSharedMemorySize, GSM_BYTES);
    cudaFuncSetAttribute(kvgemm_kernel, cudaFuncAttributeMaxDynamicSharedMemorySize, GSM_BYTES);
    cudaFuncSetAttribute(fcln_kernel,   cudaFuncAttributeMaxDynamicSharedMemorySize, FSM_BYTES);

    static cudaStream_t s_side = nullptr;
    static cudaEvent_t ev_fork = nullptr, ev_join = nullptr;
    if (s_side == nullptr) {
        cudaStreamCreateWithFlags(&s_side, cudaStreamNonBlocking);
        cudaEventCreateWithFlags(&ev_fork, cudaEventDisableTiming);
        cudaEventCreateWithFlags(&ev_join, cudaEventDisableTiming);
    }

    const float qsc = 0.17677669529663687f * 1.4426950408889634f;   // log2e/sqrt(dk)

    // fork FIRST: Q projection + Gamma need only raw inputs, not prep outputs
    cudaEventRecord(ev_fork, 0);
    cudaStreamWaitEvent(s_side, ev_fork, 0);
    mgemm_kernel<<<dim3(2, BB * LL / 128), 256, GSM_BYTES, s_side>>>(
        x_spatial, Wq, nullptr, p_Qh, SD, 0, qsc);
    mgemm_kernel<<<dim3(2, BB * MN / 128), 256, GSM_BYTES, s_side>>>(
        x_velocity, Wg, p_gamma, nullptr, VD, 1, 1.f);
    cudaEventRecord(ev_join, s_side);

    // main chain: prep -> conv -> pe -> K+V
    prep_kernel<<<84 + 640 + 512, 256>>>(ms_w3, ms_w5, ms_w7, Wk, Wv, fc_w, rel_emb);
    conv_kernel<<<BB * 16 * 2, 128, CONV_SMEM>>>(x_velocity, ms_b3, ms_b5, ms_b7);
    pe_kernel<<<BB * MN * 96 / 256, 256>>>(rel_emb, dw_w, dw_b);
    kvgemm_kernel<<<dim3(4, BB * MN / 128), 256, GSM_BYTES>>>();

    cudaStreamWaitEvent(0, ev_join, 0);
    attn_kernel<<<BB * NH * 4, 256, ATT_SMEM>>>();
    fcln_kernel<<<BB * LL / 64, 256, FSM_BYTES>>>(fc_b, x_spatial, ln_w, ln_b, out);
}

// round 16
// speedup vs baseline: 1.0545x; 1.0545x over previous
#include <cuda_runtime.h>
#include <cuda_fp16.h>
#include <math.h>
#include <stdint.h>

#define BB 32
#define LL 1024
#define MN 512
#define SD 256
#define VD 64
#define D3 192
#define DM 256
#define NH 8
#define DK 32

// ---------------- scratch (device globals; no allocation allowed) ----------------
__device__ float g_pos_sum[MN * D3];
__device__ float g_gamma[BB * MN * DM];
__device__ __half g_xmh[BB * MN * D3];
__device__ __half g_peh[BB * MN * D3];
__device__ __half g_Qh[BB * LL * DM];
__device__ __half g_Kh[BB * MN * DM];
__device__ __half g_Vh[BB * MN * DM];
__device__ __half g_attnh[BB * LL * DM];
__device__ __half g_Wkh[DM * D3];
__device__ __half g_Wvh[DM * D3];
__device__ __half g_Wfh[DM * DM];
__device__ uint2 g_wf[7 * 24 * 4 * 32];   // conv weights, fragment-major coalesced

// ================= helpers =========================================================
__device__ __forceinline__ uint32_t h2u(float a, float b) {
    __half2 h = __floats2half2_rn(a, b);
    return *(uint32_t*)&h;
}
__device__ __forceinline__ float2 u2f2(uint32_t u) {
    return __half22float2(*(__half2*)&u);
}
__device__ __forceinline__ uint32_t f22h2(float lo, float hi) {
    uint32_t r;
    asm("cvt.rn.f16x2.f32 %0, %1, %2;" : "=r"(r) : "f"(hi), "f"(lo));
    return r;
}
__device__ __forceinline__ uint32_t ex2h2(uint32_t x) {
    uint32_t r;
    asm("ex2.approx.f16x2 %0, %1;" : "=r"(r) : "r"(x));
    return r;
}
__device__ __forceinline__ void mma_f16(float* c, uint4 a, uint2 b) {
    asm("mma.sync.aligned.m16n8k16.row.col.f32.f16.f16.f32 "
        "{%0,%1,%2,%3}, {%4,%5,%6,%7}, {%8,%9}, {%0,%1,%2,%3};"
        : "+f"(c[0]), "+f"(c[1]), "+f"(c[2]), "+f"(c[3])
        : "r"(a.x), "r"(a.y), "r"(a.z), "r"(a.w), "r"(b.x), "r"(b.y));
}
__device__ __forceinline__ void ldmx4(uint4& v, uint32_t addr) {
    asm volatile("ldmatrix.sync.aligned.m8n8.x4.shared.b16 {%0,%1,%2,%3}, [%4];"
        : "=r"(v.x), "=r"(v.y), "=r"(v.z), "=r"(v.w) : "r"(addr));
}
__device__ __forceinline__ uint32_t smem_u32(const void* p) {
    uint32_t a;
    asm("{ .reg .u64 t; cvta.to.shared.u64 t, %1; cvt.u32.u64 %0, t; }" : "=r"(a) : "l"(p));
    return a;
}

// lane-constant fragment offsets (A m16k16 / B 2x(n8k16) ldmatrix.x4 maps)
#define LANE_FRAG_OFFS(lane)                                   \
    int rowA = (lane) & 15;                                    \
    int kA = ((lane) >> 4) * 16;          /* bytes */          \
    int rowB = ((lane) & 7) + (((lane) >> 4) << 3);            \
    int kB = ((lane) & 8) * 2;            /* bytes */

// GEMM smem: half tiles, 128 rows x 32 halves, padded to 40 halves (80 B/row)
#define GS_AS 20
#define GS_TILE (128 * GS_AS)
#define GSM_BYTES (4 * GS_TILE * 4)   // 40960 B

// ---------------- float-input GEMM (Q / Gamma; side stream) ------------------------
__global__ void __launch_bounds__(256, 2) mgemm_kernel(
    const float* __restrict__ A, const float* __restrict__ W,
    float* __restrict__ Cf, __half* __restrict__ Ch,
    int Kd, int sigmoidFlag, float outScale) {
    extern __shared__ uint32_t gsm[];
    uint32_t sb = smem_u32(gsm);
    int tid = threadIdx.x;
    int lane = tid & 31, wid = tid >> 5;
    int mw = wid & 1, nw = wid >> 1;
    int qd = lane >> 2, pd = lane & 3;
    LANE_FRAG_OFFS(lane);
    int m0 = blockIdx.y * 128;
    int n0b = blockIdx.x * 128;
    int NC = Kd >> 5;

    float acc[4][4][4];
    #pragma unroll
    for (int t = 0; t < 4; t++)
        #pragma unroll
        for (int u = 0; u < 4; u++)
            #pragma unroll
            for (int j = 0; j < 4; j++) acc[t][u][j] = 0.f;

    {
        uint32_t* Ad = gsm;
        uint32_t* Bd = gsm + 2 * GS_TILE;
        #pragma unroll
        for (int i = 0; i < 4; i++) {
            int g = tid + i * 256;
            int row = g >> 3, q = g & 7;
            float4 va = *(const float4*)&A[(size_t)(m0 + row) * Kd + q * 4];
            float4 vb = *(const float4*)&W[(size_t)(n0b + row) * Kd + q * 4];
            *(uint2*)&Ad[row * GS_AS + q * 2] = make_uint2(h2u(va.x, va.y), h2u(va.z, va.w));
            *(uint2*)&Bd[row * GS_AS + q * 2] = make_uint2(h2u(vb.x, vb.y), h2u(vb.z, vb.w));
        }
    }
    __syncthreads();

    for (int c = 0; c < NC; c++) {
        uint32_t Ab = sb + ((c & 1) ? GS_TILE * 4 : 0);
        uint32_t Bb = sb + 2 * GS_TILE * 4 + ((c & 1) ? GS_TILE * 4 : 0);

        uint2 pah[4], pbh[4];
        if (c + 1 < NC) {
            int kk = (c + 1) * 32;
            #pragma unroll
            for (int i = 0; i < 4; i++) {
                int g = tid + i * 256;
                int row = g >> 3, q = g & 7;
                float4 va = *(const float4*)&A[(size_t)(m0 + row) * Kd + kk + q * 4];
                float4 vb = *(const float4*)&W[(size_t)(n0b + row) * Kd + kk + q * 4];
                pah[i] = make_uint2(h2u(va.x, va.y), h2u(va.z, va.w));
                pbh[i] = make_uint2(h2u(vb.x, vb.y), h2u(vb.z, vb.w));
            }
        }

        #pragma unroll
        for (int ks = 0; ks < 2; ks++) {
            uint4 av[4];
            uint2 bv[4];
            #pragma unroll
            for (int t = 0; t < 4; t++)
                ldmx4(av[t], Ab + (mw * 64 + t * 16 + rowA) * 80 + ks * 32 + kA);
            uint4 b01, b23;
            ldmx4(b01, Bb + (nw * 32 + rowB) * 80 + ks * 32 + kB);
            ldmx4(b23, Bb + (nw * 32 + 16 + rowB) * 80 + ks * 32 + kB);
            bv[0] = make_uint2(b01.x, b01.y); bv[1] = make_uint2(b01.z, b01.w);
            bv[2] = make_uint2(b23.x, b23.y); bv[3] = make_uint2(b23.z, b23.w);
            #pragma unroll
            for (int t = 0; t < 4; t++)
                #pragma unroll
                for (int u = 0; u < 4; u++)
                    mma_f16(acc[t][u], av[t], bv[u]);
        }

        if (c + 1 < NC) {
            __syncthreads();
            uint32_t* Ad = gsm + (((c + 1) & 1) ? GS_TILE : 0);
            uint32_t* Bd = gsm + 2 * GS_TILE + (((c + 1) & 1) ? GS_TILE : 0);
            #pragma unroll
            for (int i = 0; i < 4; i++) {
                int g = tid + i * 256;
                int row = g >> 3, q = g & 7;
                *(uint2*)&Ad[row * GS_AS + q * 2] = pah[i];
                *(uint2*)&Bd[row * GS_AS + q * 2] = pbh[i];
            }
            __syncthreads();
        }
    }

    #pragma unroll
    for (int t = 0; t < 4; t++) {
        int r0 = m0 + mw * 64 + t * 16 + qd;
        #pragma unroll
        for (int u = 0; u < 4; u++) {
            int col = n0b + nw * 32 + u * 8 + pd * 2;
            float v0 = acc[t][u][0], v1 = acc[t][u][1];
            float v2 = acc[t][u][2], v3 = acc[t][u][3];
            if (Ch) {
                *(uint32_t*)&Ch[(size_t)r0 * DM + col] = h2u(v0 * outScale, v1 * outScale);
                *(uint32_t*)&Ch[(size_t)(r0 + 8) * DM + col] = h2u(v2 * outScale, v3 * outScale);
            } else {
                if (sigmoidFlag) {
                    v0 = 1.f / (1.f + __expf(-v0));
                    v1 = 1.f / (1.f + __expf(-v1));
                    v2 = 1.f / (1.f + __expf(-v2));
                    v3 = 1.f / (1.f + __expf(-v3));
                }
                *(float2*)&Cf[(size_t)r0 * DM + col]       = make_float2(v0, v1);
                *(float2*)&Cf[(size_t)(r0 + 8) * DM + col] = make_float2(v2, v3);
            }
        }
    }
}

// ---------------- K+V fused GEMM: half A (pe), half W, ldmatrix fragments ----------
__global__ void __launch_bounds__(256, 2) kvgemm_kernel() {
    extern __shared__ uint32_t gsm[];
    uint32_t sb = smem_u32(gsm);
    int tid = threadIdx.x;
    int lane = tid & 31, wid = tid >> 5;
    int mw = wid & 1, nw = wid >> 1;
    int qd = lane >> 2, pd = lane & 3;
    LANE_FRAG_OFFS(lane);
    int bx = blockIdx.x;
    int n0b = (bx & 1) * 128;
    const __half* A = g_peh;
    const __half* W = (bx >> 1) ? g_Wvh : g_Wkh;
    __half* C = (bx >> 1) ? g_Vh : g_Kh;
    int m0 = blockIdx.y * 128;
    const int NC = 6;

    float acc[4][4][4];
    #pragma unroll
    for (int t = 0; t < 4; t++)
        #pragma unroll
        for (int u = 0; u < 4; u++)
            #pragma unroll
            for (int j = 0; j < 4; j++) acc[t][u][j] = 0.f;

    {
        uint32_t* Ad = gsm;
        uint32_t* Bd = gsm + 2 * GS_TILE;
        #pragma unroll
        for (int i = 0; i < 2; i++) {
            int g = tid + i * 256;
            int row = g >> 2, q = g & 3;
            *(uint4*)&Ad[row * GS_AS + q * 4] =
                *(const uint4*)&A[(size_t)(m0 + row) * D3 + q * 8];
            *(uint4*)&Bd[row * GS_AS + q * 4] =
                *(const uint4*)&W[(size_t)(n0b + row) * D3 + q * 8];
        }
    }
    __syncthreads();

    for (int c = 0; c < NC; c++) {
        uint32_t Ab = sb + ((c & 1) ? GS_TILE * 4 : 0);
        uint32_t Bb = sb + 2 * GS_TILE * 4 + ((c & 1) ? GS_TILE * 4 : 0);

        uint4 pah[2], pbh[2];
        if (c + 1 < NC) {
            int kk = (c + 1) * 32;
            #pragma unroll
            for (int i = 0; i < 2; i++) {
                int g = tid + i * 256;
                int row = g >> 2, q = g & 3;
                pah[i] = *(const uint4*)&A[(size_t)(m0 + row) * D3 + kk + q * 8];
                pbh[i] = *(const uint4*)&W[(size_t)(n0b + row) * D3 + kk + q * 8];
            }
        }

        #pragma unroll
        for (int ks = 0; ks < 2; ks++) {
            uint4 av[4];
            uint2 bv[4];
            #pragma unroll
            for (int t = 0; t < 4; t++)
                ldmx4(av[t], Ab + (mw * 64 + t * 16 + rowA) * 80 + ks * 32 + kA);
            uint4 b01, b23;
            ldmx4(b01, Bb + (nw * 32 + rowB) * 80 + ks * 32 + kB);
            ldmx4(b23, Bb + (nw * 32 + 16 + rowB) * 80 + ks * 32 + kB);
            bv[0] = make_uint2(b01.x, b01.y); bv[1] = make_uint2(b01.z, b01.w);
            bv[2] = make_uint2(b23.x, b23.y); bv[3] = make_uint2(b23.z, b23.w);
            #pragma unroll
            for (int t = 0; t < 4; t++)
                #pragma unroll
                for (int u = 0; u < 4; u++)
                    mma_f16(acc[t][u], av[t], bv[u]);
        }

        if (c + 1 < NC) {
            __syncthreads();
            uint32_t* Ad = gsm + (((c + 1) & 1) ? GS_TILE : 0);
            uint32_t* Bd = gsm + 2 * GS_TILE + (((c + 1) & 1) ? GS_TILE : 0);
            #pragma unroll
            for (int i = 0; i < 2; i++) {
                int g = tid + i * 256;
                int row = g >> 2, q = g & 3;
                *(uint4*)&Ad[row * GS_AS + q * 4] = pah[i];
                *(uint4*)&Bd[row * GS_AS + q * 4] = pbh[i];
            }
            __syncthreads();
        }
    }

    #pragma unroll
    for (int t = 0; t < 4; t++) {
        int r0 = m0 + mw * 64 + t * 16 + qd;
        #pragma unroll
        for (int u = 0; u < 4; u++) {
            int col = n0b + nw * 32 + u * 8 + pd * 2;
            *(uint32_t*)&C[(size_t)r0 * DM + col] = h2u(acc[t][u][0], acc[t][u][1]);
            *(uint32_t*)&C[(size_t)(r0 + 8) * DM + col] = h2u(acc[t][u][2], acc[t][u][3]);
        }
    }
}

// ---------------- fused prep: conv wf + Wk/Wv/Wf halves + pos_sum ------------------
__global__ void prep_kernel(const float* __restrict__ w3, const float* __restrict__ w5,
                            const float* __restrict__ w7, const float* __restrict__ Wk,
                            const float* __restrict__ Wv, const float* __restrict__ Wf,
                            const float* __restrict__ emb) {
    int bid = blockIdx.x;
    int tid = threadIdx.x;
    if (bid < 84) {                        // conv weights fragment-major: 21504 uint2
        int idx = bid * 256 + tid;
        if (idx < 21504) {
            int lane = idx & 31;
            int ks = (idx >> 5) & 3;
            int rem = idx >> 7;            // tp*24 + ct
            int ct = rem % 24;
            int tp = rem / 24;
            int qd = lane >> 2, pd = lane & 3;
            int c = ct * 8 + qd;
            int kw0 = ks * 8 + pd;
            float v[4];
            #pragma unroll
            for (int e = 0; e < 4; e++) {
                int i = (kw0 + (e >> 1) * 4) * 2 + (e & 1);
                float val = 0.f;
                if (c < 64)       { if (tp >= 2 && tp <= 4) val = w3[(c * 64 + i) * 3 + (tp - 2)]; }
                else if (c < 128) { int cc = c - 64; if (tp >= 1 && tp <= 5) val = w5[(cc * 64 + i) * 5 + (tp - 1)]; }
                else              { int cc = c - 128; val = w7[(cc * 64 + i) * 7 + tp]; }
                v[e] = val;
            }
            g_wf[idx] = make_uint2(h2u(v[0], v[1]), h2u(v[2], v[3]));
        }
    } else if (bid < 84 + 640) {           // Wk/Wv/Wf: 163840 halves
        int idx = (bid - 84) * 256 + tid;
        const int NK = DM * D3;
        if (idx < NK) g_Wkh[idx] = __float2half_rn(Wk[idx]);
        else if (idx < 2 * NK) g_Wvh[idx - NK] = __float2half_rn(Wv[idx - NK]);
        else if (idx < 2 * NK + DM * DM) g_Wfh[idx - 2 * NK] = __float2half_rn(Wf[idx - 2 * NK]);
    } else {                               // pos_sum: 512 rows x 192
        int j = bid - (84 + 640);
        int d = tid;
        if (d < D3) {
            float acc = 0.f;
            #pragma unroll
            for (int delta = -29; delta <= 29; delta++) {
                int i = j - delta;
                if (i >= 0 && i < MN) acc += emb[(delta + 30) * D3 + d];
            }
            int cpos = j - 29;
            if (cpos > 0) acc += (float)cpos * emb[60 * D3 + d];
            int cneg = 482 - j;
            if (cneg > 0) acc += (float)cneg * emb[0 * D3 + d];
            g_pos_sum[j * D3 + d] = acc;
        }
    }
}

// ---------------- multi-scale conv: channel-split, coalesced weight frags ----------
#define CXR2 38
#define CXS 36
#define CONV_SMEM (CXR2 * CXS * 4)   // 5472 B

__device__ __forceinline__ constexpr int conv_abase(int tp) {
    return (tp >= 2 && tp <= 4) ? 0 : ((tp == 1 || tp == 5) ? 64 : 128);
}

__global__ void __launch_bounds__(128) conv_kernel(
    const float* __restrict__ xv, const float* __restrict__ b3,
    const float* __restrict__ b5, const float* __restrict__ b7) {
    extern __shared__ uint32_t csm[];
    uint32_t* xvs = csm;
    uint32_t xb = smem_u32(csm);
    int blk = blockIdx.x;              // ((b*16 + sblk) << 1) | chalf
    int ch = blk & 1;
    int sblk = (blk >> 1) & 15;
    int b = blk >> 5;
    int s0 = sblk * 32;
    int cbase = ch * 96;
    int tid = threadIdx.x;
    int lane = tid & 31, nw = tid >> 5;
    int qd = lane >> 2, pd = lane & 3;
    LANE_FRAG_OFFS(lane);
    int ct0 = ch * 12 + nw * 3;        // this warp's first 8-channel tile

    for (int g = tid; g < CXR2 * 16; g += 128) {
        int row = g >> 4, c4 = g & 15;
        int s = s0 - 3 + row;
        float4 v = make_float4(0.f, 0.f, 0.f, 0.f);
        if (s >= 0 && s < MN) v = *(const float4*)&xv[((size_t)b * MN + s) * VD + c4 * 4];
        *(uint2*)&xvs[row * CXS + c4 * 2] = make_uint2(h2u(v.x, v.y), h2u(v.z, v.w));
    }
    __syncthreads();

    float acc[2][3][4];
    #pragma unroll
    for (int t = 0; t < 2; t++)
        #pragma unroll
        for (int u = 0; u < 3; u++)
            #pragma unroll
            for (int j = 0; j < 4; j++) acc[t][u][j] = 0.f;

    uint2 bvb[2][3];
    {
        const int ab0 = conv_abase(0);
        #pragma unroll
        for (int u = 0; u < 3; u++) {
            if ((ct0 + u) * 8 >= ab0)
                bvb[0][u] = __ldg(&g_wf[(((0 * 24 + ct0 + u) * 4 + 0) << 5) + lane]);
        }
    }

    #pragma unroll
    for (int step = 0; step < 28; step++) {
        const int tp = step >> 2, ks = step & 3;
        const int abase = conv_abase(tp);

        if (step + 1 < 28) {
            const int tp2 = (step + 1) >> 2, ks2 = (step + 1) & 3;
            const int ab2 = conv_abase(tp2);
            #pragma unroll
            for (int u = 0; u < 3; u++) {
                if ((ct0 + u) * 8 >= ab2)
                    bvb[(step + 1) & 1][u] =
                        __ldg(&g_wf[(((tp2 * 24 + ct0 + u) * 4 + ks2) << 5) + lane]);
            }
        }

        uint4 av[2];
        #pragma unroll
        for (int t = 0; t < 2; t++)
            ldmx4(av[t], xb + (t * 16 + rowA + tp) * 144 + ks * 32 + kA);
        #pragma unroll
        for (int u = 0; u < 3; u++) {
            if ((ct0 + u) * 8 >= abase) {
                #pragma unroll
                for (int t = 0; t < 2; t++)
                    mma_f16(acc[t][u], av[t], bvb[step & 1][u]);
            }
        }
    }

    #pragma unroll
    for (int t = 0; t < 2; t++) {
        int s = s0 + t * 16 + qd;
        #pragma unroll
        for (int u = 0; u < 3; u++) {
            int col = cbase + nw * 24 + u * 8 + pd * 2;
            float bb0 = col < 64 ? b3[col] : (col < 128 ? b5[col - 64] : b7[col - 128]);
            int c1 = col + 1;
            float bb1 = c1 < 64 ? b3[c1] : (c1 < 128 ? b5[c1 - 64] : b7[c1 - 128]);
            *(uint32_t*)&g_xmh[((size_t)b * MN + s) * D3 + col] =
                h2u(acc[t][u][0] + bb0, acc[t][u][1] + bb1);
            *(uint32_t*)&g_xmh[((size_t)b * MN + s + 8) * D3 + col] =
                h2u(acc[t][u][2] + bb0, acc[t][u][3] + bb1);
        }
    }
}

// ---------------- rel-pos encoding: half2-vectorized -------------------------------
__global__ void pe_kernel(const float* __restrict__ emb,
                          const float* __restrict__ dww, const float* __restrict__ dwb) {
    int idx = blockIdx.x * 256 + threadIdx.x;   // half2 index; total BB*MN*96
    int d2 = idx % 96;
    int r = idx / 96;
    int j = r & (MN - 1);
    int d = d2 * 2;
    const uint32_t* xm2 = (const uint32_t*)g_xmh;
    uint32_t* pe2 = (uint32_t*)g_peh;
    float2 xc = u2f2(xm2[idx]);
    float fC0 = xc.x + emb[30 * D3 + d];
    float fC1 = xc.y + emb[30 * D3 + d + 1];
    float fL0 = 0.f, fL1 = 0.f, fR0 = 0.f, fR1 = 0.f;
    if (j > 0) {
        float2 xl = u2f2(xm2[idx - 96]);
        fL0 = xl.x + emb[29 * D3 + d];
        fL1 = xl.y + emb[29 * D3 + d + 1];
    }
    if (j < MN - 1) {
        float2 xr = u2f2(xm2[idx + 96]);
        fR0 = xr.x + emb[31 * D3 + d];
        fR1 = xr.y + emb[31 * D3 + d + 1];
    }
    float dg0 = fL0 * dww[d * 3 + 0] + fC0 * dww[d * 3 + 1] + fR0 * dww[d * 3 + 2] + dwb[d];
    float dg1 = fL1 * dww[d * 3 + 3] + fC1 * dww[d * 3 + 4] + fR1 * dww[d * 3 + 5] + dwb[d + 1];
    float o0 = xc.x + (g_pos_sum[j * D3 + d] - fC0 + dg0) * (1.0f / (float)MN);
    float o1 = xc.y + (g_pos_sum[j * D3 + d + 1] - fC1 + dg1) * (1.0f / (float)MN);
    pe2[idx] = h2u(o0, o1);
}

// ---------------- attention: ldmatrix K/V, f16x2 exp (V loads before QK) -----------
#define AK_STRIDE 20
#define AV_STRIDE 260
#define ATT_SMEM ((MN * AK_STRIDE + DK * AV_STRIDE) * 4)   // 74240 B

__global__ void __launch_bounds__(256, 2) attn_kernel() {
    extern __shared__ uint32_t ash[];
    uint32_t* Ks = ash;
    uint32_t* VT = ash + MN * AK_STRIDE;
    uint32_t Kb = smem_u32(ash);
    uint32_t Vb = Kb + MN * AK_STRIDE * 4;
    int blk = blockIdx.x;
    int qblk = blk & 3;
    int h = (blk >> 2) & 7;
    int b = blk >> 5;
    int tid = threadIdx.x;
    int lane = tid & 31, wid = tid >> 5;
    int qd = lane >> 2, pd = lane & 3;
    LANE_FRAG_OFFS(lane);
    (void)rowA; (void)kA;

    const __half* Kg = g_Kh + (size_t)b * MN * DM + h * DK;
    for (int i = tid; i < MN * 4; i += 256) {
        int s = i >> 2, c8 = i & 3;
        uint4 kv = *(const uint4*)&Kg[(size_t)s * DM + c8 * 8];
        *(uint4*)&Ks[s * AK_STRIDE + c8 * 4] = kv;
    }
    const __half* Vg = g_Vh + (size_t)b * MN * DM + h * DK;
    for (int g = tid; g < 1024; g += 256) {
        int spair = g >> 2, q = g & 3;
        int s = spair * 2;
        uint4 a = *(const uint4*)&Vg[(size_t)s * DM + q * 8];
        uint4 bq = *(const uint4*)&Vg[(size_t)(s + 1) * DM + q * 8];
        int d0 = q * 8;
        VT[(d0 + 0) * AV_STRIDE + spair] = (a.x & 0xFFFFu) | (bq.x << 16);
        VT[(d0 + 1) * AV_STRIDE + spair] = (a.x >> 16) | (bq.x & 0xFFFF0000u);
        VT[(d0 + 2) * AV_STRIDE + spair] = (a.y & 0xFFFFu) | (bq.y << 16);
        VT[(d0 + 3) * AV_STRIDE + spair] = (a.y >> 16) | (bq.y & 0xFFFF0000u);
        VT[(d0 + 4) * AV_STRIDE + spair] = (a.z & 0xFFFFu) | (bq.z << 16);
        VT[(d0 + 5) * AV_STRIDE + spair] = (a.z >> 16) | (bq.z & 0xFFFF0000u);
        VT[(d0 + 6) * AV_STRIDE + spair] = (a.w & 0xFFFFu) | (bq.w << 16);
        VT[(d0 + 7) * AV_STRIDE + spair] = (a.w >> 16) | (bq.w & 0xFFFF0000u);
    }
    __syncthreads();

    int m0 = qblk * 256 + wid * 32;
    const __half* Qg = g_Qh + ((size_t)b * LL + m0) * DM + h * DK;
    uint4 aq[2][2];
    #pragma unroll
    for (int t = 0; t < 2; t++)
        #pragma unroll
        for (int ks = 0; ks < 2; ks++) {
            int r = t * 16 + qd;
            int c = ks * 16 + pd * 2;
            aq[t][ks].x = *(const uint32_t*)&Qg[(size_t)r * DM + c];
            aq[t][ks].y = *(const uint32_t*)&Qg[(size_t)(r + 8) * DM + c];
            aq[t][ks].z = *(const uint32_t*)&Qg[(size_t)r * DM + c + 8];
            aq[t][ks].w = *(const uint32_t*)&Qg[(size_t)(r + 8) * DM + c + 8];
        }

    float o[2][4][4];
    #pragma unroll
    for (int t = 0; t < 2; t++)
        #pragma unroll
        for (int nv = 0; nv < 4; nv++)
            #pragma unroll
            for (int j = 0; j < 4; j++) o[t][nv][j] = 0.f;
    float rs[2][2] = {{0.f, 0.f}, {0.f, 0.f}};

    for (int s0 = 0; s0 < MN; s0 += 16) {
        // V fragments first: independent of QK, latency overlaps the mma below
        uint2 bv[4];
        {
            uint4 m0v, m1v;
            ldmx4(m0v, Vb + rowB * 1040 + s0 * 2 + kB);
            ldmx4(m1v, Vb + (16 + rowB) * 1040 + s0 * 2 + kB);
            bv[0] = make_uint2(m0v.x, m0v.y); bv[1] = make_uint2(m0v.z, m0v.w);
            bv[2] = make_uint2(m1v.x, m1v.y); bv[3] = make_uint2(m1v.z, m1v.w);
        }

        uint2 bk[2][2];
        #pragma unroll
        for (int ks = 0; ks < 2; ks++) {
            uint4 m;
            ldmx4(m, Kb + (s0 + rowB) * 80 + ks * 32 + kB);
            bk[0][ks] = make_uint2(m.x, m.y);
            bk[1][ks] = make_uint2(m.z, m.w);
        }

        float c[2][2][4];
        #pragma unroll
        for (int t = 0; t < 2; t++)
            #pragma unroll
            for (int n = 0; n < 2; n++) {
                #pragma unroll
                for (int j = 0; j < 4; j++) c[t][n][j] = 0.f;
                #pragma unroll
                for (int ks = 0; ks < 2; ks++)
                    mma_f16(c[t][n], aq[t][ks], bk[n][ks]);
            }

        // exp in f16x2; rowsum via HADD2 then float accumulate
        uint4 ap[2];
        #pragma unroll
        for (int t = 0; t < 2; t++) {
            uint32_t p0 = ex2h2(f22h2(c[t][0][0], c[t][0][1]));
            uint32_t p1 = ex2h2(f22h2(c[t][0][2], c[t][0][3]));
            uint32_t p2 = ex2h2(f22h2(c[t][1][0], c[t][1][1]));
            uint32_t p3 = ex2h2(f22h2(c[t][1][2], c[t][1][3]));
            ap[t] = make_uint4(p0, p1, p2, p3);
            __half2 sh0 = __hadd2(*(__half2*)&p0, *(__half2*)&p2);
            __half2 sh1 = __hadd2(*(__half2*)&p1, *(__half2*)&p3);
            float2 f0 = __half22float2(sh0);
            float2 f1 = __half22float2(sh1);
            rs[t][0] += f0.x + f0.y;
            rs[t][1] += f1.x + f1.y;
        }

        // O += P V
        #pragma unroll
        for (int t = 0; t < 2; t++)
            #pragma unroll
            for (int nv = 0; nv < 4; nv++)
                mma_f16(o[t][nv], ap[t], bv[nv]);
    }

    __half* Ah = g_attnh;
    #pragma unroll
    for (int t = 0; t < 2; t++) {
        #pragma unroll
        for (int r = 0; r < 2; r++) {
            rs[t][r] += __shfl_xor_sync(0xFFFFFFFFu, rs[t][r], 1);
            rs[t][r] += __shfl_xor_sync(0xFFFFFFFFu, rs[t][r], 2);
        }
        float inv0 = 1.f / rs[t][0];
        float inv1 = 1.f / rs[t][1];
        int r0 = m0 + t * 16 + qd;
        #pragma unroll
        for (int nv = 0; nv < 4; nv++) {
            int col = h * DK + nv * 8 + pd * 2;
            *(uint32_t*)&Ah[((size_t)b * LL + r0) * DM + col] =
                h2u(o[t][nv][0] * inv0, o[t][nv][1] * inv0);
            *(uint32_t*)&Ah[((size_t)b * LL + r0 + 8) * DM + col] =
                h2u(o[t][nv][2] * inv1, o[t][nv][3] * inv1);
        }
    }
}

// ---------------- fc GEMM fused with gate + residual + LayerNorm ------------------
#define FA_TILE (64 * GS_AS)
#define FB_TILE (256 * GS_AS)
#define FSM_BYTES ((2 * FA_TILE + 2 * FB_TILE + 512) * 4)   // 53248 B

__global__ void __launch_bounds__(256, 2) fcln_kernel(
    const float* __restrict__ fb, const float* __restrict__ xs,
    const float* __restrict__ lnw, const float* __restrict__ lnb,
    float* __restrict__ out) {
    extern __shared__ uint32_t fsm[];
    uint32_t sb = smem_u32(fsm);
    float* red = (float*)(fsm + 2 * FA_TILE + 2 * FB_TILE);
    const __half* A = g_attnh;
    const __half* Wf = g_Wfh;
    int tid = threadIdx.x;
    int lane = tid & 31, wid = tid >> 5;
    int mw = wid & 1, nw = wid >> 1;
    int qd = lane >> 2, pd = lane & 3;
    LANE_FRAG_OFFS(lane);
    int row0 = blockIdx.x * 64;
    int b = row0 >> 10;
    const int NC = 8;

    float acc[2][8][4];
    #pragma unroll
    for (int t = 0; t < 2; t++)
        #pragma unroll
        for (int u = 0; u < 8; u++)
            #pragma unroll
            for (int j = 0; j < 4; j++) acc[t][u][j] = 0.f;

    {
        uint32_t* Ad = fsm;
        uint32_t* Bd = fsm + 2 * FA_TILE;
        #pragma unroll
        for (int i = 0; i < 5; i++) {
            int g = tid + i * 256;
            if (g < 256) {
                int row = g >> 2, q = g & 3;
                *(uint4*)&Ad[row * GS_AS + q * 4] =
                    *(const uint4*)&A[(size_t)(row0 + row) * DM + q * 8];
            } else {
                int j = g - 256;
                int row = j >> 2, q = j & 3;
                *(uint4*)&Bd[row * GS_AS + q * 4] =
                    *(const uint4*)&Wf[(size_t)row * DM + q * 8];
            }
        }
    }
    __syncthreads();

    for (int c = 0; c < NC; c++) {
        uint32_t Ab = sb + ((c & 1) ? FA_TILE * 4 : 0);
        uint32_t Bb = sb + 2 * FA_TILE * 4 + ((c & 1) ? FB_TILE * 4 : 0);

        uint4 pf[5];
        if (c + 1 < NC) {
            int kk = (c + 1) * 32;
            #pragma unroll
            for (int i = 0; i < 5; i++) {
                int g = tid + i * 256;
                if (g < 256) {
                    int row = g >> 2, q = g & 3;
                    pf[i] = *(const uint4*)&A[(size_t)(row0 + row) * DM + kk + q * 8];
                } else {
                    int j = g - 256;
                    int row = j >> 2, q = j & 3;
                    pf[i] = *(const uint4*)&Wf[(size_t)row * DM + kk + q * 8];
                }
            }
        }

        #pragma unroll
        for (int ks = 0; ks < 2; ks++) {
            uint4 av[2];
            uint2 bv[8];
            #pragma unroll
            for (int t = 0; t < 2; t++)
                ldmx4(av[t], Ab + (mw * 32 + t * 16 + rowA) * 80 + ks * 32 + kA);
            #pragma unroll
            for (int u2 = 0; u2 < 4; u2++) {
                uint4 m;
                ldmx4(m, Bb + (nw * 64 + u2 * 16 + rowB) * 80 + ks * 32 + kB);
                bv[u2 * 2] = make_uint2(m.x, m.y);
                bv[u2 * 2 + 1] = make_uint2(m.z, m.w);
            }
            #pragma unroll
            for (int t = 0; t < 2; t++)
                #pragma unroll
                for (int u = 0; u < 8; u++)
                    mma_f16(acc[t][u], av[t], bv[u]);
        }

        if (c + 1 < NC) {
            __syncthreads();
            uint32_t* Ad = fsm + (((c + 1) & 1) ? FA_TILE : 0);
            uint32_t* Bd = fsm + 2 * FA_TILE + (((c + 1) & 1) ? FB_TILE : 0);
            #pragma unroll
            for (int i = 0; i < 5; i++) {
                int g = tid + i * 256;
                if (g < 256) {
                    int row = g >> 2, q = g & 3;
                    *(uint4*)&Ad[row * GS_AS + q * 4] = pf[i];
                } else {
                    int j = g - 256;
                    int row = j >> 2, q = j & 3;
                    *(uint4*)&Bd[row * GS_AS + q * 4] = pf[i];
                }
            }
            __syncthreads();
        }
    }

    __syncthreads();
    #pragma unroll
    for (int t = 0; t < 2; t++) {
        #pragma unroll
        for (int hf = 0; hf < 2; hf++) {
            int lr = mw * 32 + t * 16 + qd + hf * 8;
            int r = row0 + lr;
            int l = r & 1023;
            const float* gam = g_gamma + ((size_t)b * MN + (l & (MN - 1))) * DM;
            const float* xr = xs + (size_t)r * DM;
            float s1 = 0.f, s2 = 0.f;
            #pragma unroll
            for (int u = 0; u < 8; u++) {
                int col = nw * 64 + u * 8 + pd * 2;
                int j0 = hf * 2;
                float v0 = xr[col] + gam[col] * (acc[t][u][j0] + fb[col]);
                float v1 = xr[col + 1] + gam[col + 1] * (acc[t][u][j0 + 1] + fb[col + 1]);
                acc[t][u][j0] = v0;
                acc[t][u][j0 + 1] = v1;
                s1 += v0 + v1;
                s2 += v0 * v0 + v1 * v1;
            }
            s1 += __shfl_xor_sync(0xFFFFFFFFu, s1, 1);
            s1 += __shfl_xor_sync(0xFFFFFFFFu, s1, 2);
            s2 += __shfl_xor_sync(0xFFFFFFFFu, s2, 1);
            s2 += __shfl_xor_sync(0xFFFFFFFFu, s2, 2);
            if (pd == 0) {
                red[nw * 64 + lr] = s1;
                red[256 + nw * 64 + lr] = s2;
            }
        }
    }
    __syncthreads();
    #pragma unroll
    for (int t = 0; t < 2; t++) {
        #pragma unroll
        for (int hf = 0; hf < 2; hf++) {
            int lr = mw * 32 + t * 16 + qd + hf * 8;
            int r = row0 + lr;
            float t1 = red[lr] + red[64 + lr] + red[128 + lr] + red[192 + lr];
            float t2 = red[256 + lr] + red[320 + lr] + red[384 + lr] + red[448 + lr];
            float mu = t1 * (1.f / 256.f);
            float var = t2 * (1.f / 256.f) - mu * mu;
            float rstd = rsqrtf(var + 1e-5f);
            #pragma unroll
            for (int u = 0; u < 8; u++) {
                int col = nw * 64 + u * 8 + pd * 2;
                int j0 = hf * 2;
                float v0 = (acc[t][u][j0] - mu) * rstd * lnw[col] + lnb[col];
                float v1 = (acc[t][u][j0 + 1] - mu) * rstd * lnw[col + 1] + lnb[col + 1];
                *(float2*)&out[(size_t)r * DM + col] = make_float2(v0, v1);
            }
        }
    }
}

// ---------------- launch: round-14 ordering (prep, then fork Q+Gamma) --------------
extern "C" void kernel_launch(void* const* d_in, const int* in_sizes, int n_in,
                              void* d_out, int out_size) {
    const float* x_spatial  = (const float*)d_in[0];
    const float* x_velocity = (const float*)d_in[1];
    const float* Wg    = (const float*)d_in[2];
    const float* ms_w3 = (const float*)d_in[3];
    const float* ms_b3 = (const float*)d_in[4];
    const float* ms_w5 = (const float*)d_in[5];
    const float* ms_b5 = (const float*)d_in[6];
    const float* ms_w7 = (const float*)d_in[7];
    const float* ms_b7 = (const float*)d_in[8];
    const float* rel_emb = (const float*)d_in[9];
    const float* dw_w  = (const float*)d_in[10];
    const float* dw_b  = (const float*)d_in[11];
    const float* Wq    = (const float*)d_in[12];
    const float* Wk    = (const float*)d_in[13];
    const float* Wv    = (const float*)d_in[14];
    const float* fc_w  = (const float*)d_in[15];
    const float* fc_b  = (const float*)d_in[16];
    const float* ln_w  = (const float*)d_in[17];
    const float* ln_b  = (const float*)d_in[18];
    float* out = (float*)d_out;

    float *p_gamma;
    __half *p_Qh;
    cudaGetSymbolAddress((void**)&p_gamma, g_gamma);
    cudaGetSymbolAddress((void**)&p_Qh,    g_Qh);

    cudaFuncSetAttribute(conv_kernel,   cudaFuncAttributeMaxDynamicSharedMemorySize, CONV_SMEM);
    cudaFuncSetAttribute(attn_kernel,   cudaFuncAttributeMaxDynamicSharedMemorySize, ATT_SMEM);
    cudaFuncSetAttribute(mgemm_kernel,  cudaFuncAttributeMaxDynamicSharedMemorySize, GSM_BYTES);
    cudaFuncSetAttribute(kvgemm_kernel, cudaFuncAttributeMaxDynamicSharedMemorySize, GSM_BYTES);
    cudaFuncSetAttribute(fcln_kernel,   cudaFuncAttributeMaxDynamicSharedMemorySize, FSM_BYTES);

    static cudaStream_t s_side = nullptr;
    static cudaEvent_t ev_fork = nullptr, ev_join = nullptr;
    if (s_side == nullptr) {
        cudaStreamCreateWithFlags(&s_side, cudaStreamNonBlocking);
        cudaEventCreateWithFlags(&ev_fork, cudaEventDisableTiming);
        cudaEventCreateWithFlags(&ev_join, cudaEventDisableTiming);
    }

    const float qsc = 0.17677669529663687f * 1.4426950408889634f;   // log2e/sqrt(dk)

    prep_kernel<<<84 + 640 + 512, 256>>>(ms_w3, ms_w5, ms_w7, Wk, Wv, fc_w, rel_emb);

    // fork: Q projection + Gamma on side stream
    cudaEventRecord(ev_fork, 0);
    cudaStreamWaitEvent(s_side, ev_fork, 0);
    mgemm_kernel<<<dim3(2, BB * LL / 128), 256, GSM_BYTES, s_side>>>(
        x_spatial, Wq, nullptr, p_Qh, SD, 0, qsc);
    mgemm_kernel<<<dim3(2, BB * MN / 128), 256, GSM_BYTES, s_side>>>(
        x_velocity, Wg, p_gamma, nullptr, VD, 1, 1.f);
    cudaEventRecord(ev_join, s_side);

    // main chain: conv (channel-split, coalesced weights) -> pe -> K+V
    conv_kernel<<<BB * 16 * 2, 128, CONV_SMEM>>>(x_velocity, ms_b3, ms_b5, ms_b7);
    pe_kernel<<<BB * MN * 96 / 256, 256>>>(rel_emb, dw_w, dw_b);
    kvgemm_kernel<<<dim3(4, BB * MN / 128), 256, GSM_BYTES>>>();

    cudaStreamWaitEvent(0, ev_join, 0);
    attn_kernel<<<BB * NH * 4, 256, ATT_SMEM>>>();
    fcln_kernel<<<BB * LL / 64, 256, FSM_BYTES>>>(fc_b, x_spatial, ln_w, ln_b, out);
}

// round 17
// speedup vs baseline: 1.0616x; 1.0067x over previous
#include <cuda_runtime.h>
#include <cuda_fp16.h>
#include <math.h>
#include <stdint.h>

#define BB 32
#define LL 1024
#define MN 512
#define SD 256
#define VD 64
#define D3 192
#define DM 256
#define NH 8
#define DK 32

// ---------------- scratch (device globals; no allocation allowed) ----------------
__device__ float g_pos_sum[MN * D3];
__device__ float g_gamma[BB * MN * DM];
__device__ __half g_xmh[BB * MN * D3];
__device__ __half g_peh[BB * MN * D3];
__device__ __half g_Qh[BB * LL * DM];
__device__ __half g_Kh[BB * MN * DM];
__device__ __half g_Vh[BB * MN * DM];
__device__ __half g_attnh[BB * LL * DM];
__device__ __half g_Wkh[DM * D3];
__device__ __half g_Wvh[DM * D3];
__device__ __half g_Wfh[DM * DM];
__device__ uint2 g_wf[7 * 24 * 4 * 32];   // conv weights, fragment-major coalesced

// ================= helpers =========================================================
__device__ __forceinline__ uint32_t h2u(float a, float b) {
    __half2 h = __floats2half2_rn(a, b);
    return *(uint32_t*)&h;
}
__device__ __forceinline__ float2 u2f2(uint32_t u) {
    return __half22float2(*(__half2*)&u);
}
__device__ __forceinline__ uint32_t f22h2(float lo, float hi) {
    uint32_t r;
    asm("cvt.rn.f16x2.f32 %0, %1, %2;" : "=r"(r) : "f"(hi), "f"(lo));
    return r;
}
__device__ __forceinline__ uint32_t ex2h2(uint32_t x) {
    uint32_t r;
    asm("ex2.approx.f16x2 %0, %1;" : "=r"(r) : "r"(x));
    return r;
}
__device__ __forceinline__ void mma_f16(float* c, uint4 a, uint2 b) {
    asm("mma.sync.aligned.m16n8k16.row.col.f32.f16.f16.f32 "
        "{%0,%1,%2,%3}, {%4,%5,%6,%7}, {%8,%9}, {%0,%1,%2,%3};"
        : "+f"(c[0]), "+f"(c[1]), "+f"(c[2]), "+f"(c[3])
        : "r"(a.x), "r"(a.y), "r"(a.z), "r"(a.w), "r"(b.x), "r"(b.y));
}
__device__ __forceinline__ void ldmx4(uint4& v, uint32_t addr) {
    asm volatile("ldmatrix.sync.aligned.m8n8.x4.shared.b16 {%0,%1,%2,%3}, [%4];"
        : "=r"(v.x), "=r"(v.y), "=r"(v.z), "=r"(v.w) : "r"(addr));
}
__device__ __forceinline__ uint32_t smem_u32(const void* p) {
    uint32_t a;
    asm("{ .reg .u64 t; cvta.to.shared.u64 t, %1; cvt.u32.u64 %0, t; }" : "=r"(a) : "l"(p));
    return a;
}

// lane-constant fragment offsets (A m16k16 / B 2x(n8k16) ldmatrix.x4 maps)
#define LANE_FRAG_OFFS(lane)                                   \
    int rowA = (lane) & 15;                                    \
    int kA = ((lane) >> 4) * 16;          /* bytes */          \
    int rowB = ((lane) & 7) + (((lane) >> 4) << 3);            \
    int kB = ((lane) & 8) * 2;            /* bytes */

// GEMM smem: half tiles, 128 rows x 32 halves, padded to 40 halves (80 B/row)
#define GS_AS 20
#define GS_TILE (128 * GS_AS)
#define GSM_BYTES (4 * GS_TILE * 4)   // 40960 B

// ---------------- float-input GEMM (Q / Gamma; side stream) ------------------------
__global__ void __launch_bounds__(256, 2) mgemm_kernel(
    const float* __restrict__ A, const float* __restrict__ W,
    float* __restrict__ Cf, __half* __restrict__ Ch,
    int Kd, int sigmoidFlag, float outScale) {
    extern __shared__ uint32_t gsm[];
    uint32_t sb = smem_u32(gsm);
    int tid = threadIdx.x;
    int lane = tid & 31, wid = tid >> 5;
    int mw = wid & 1, nw = wid >> 1;
    int qd = lane >> 2, pd = lane & 3;
    LANE_FRAG_OFFS(lane);
    int m0 = blockIdx.y * 128;
    int n0b = blockIdx.x * 128;
    int NC = Kd >> 5;

    float acc[4][4][4];
    #pragma unroll
    for (int t = 0; t < 4; t++)
        #pragma unroll
        for (int u = 0; u < 4; u++)
            #pragma unroll
            for (int j = 0; j < 4; j++) acc[t][u][j] = 0.f;

    {
        uint32_t* Ad = gsm;
        uint32_t* Bd = gsm + 2 * GS_TILE;
        #pragma unroll
        for (int i = 0; i < 4; i++) {
            int g = tid + i * 256;
            int row = g >> 3, q = g & 7;
            float4 va = *(const float4*)&A[(size_t)(m0 + row) * Kd + q * 4];
            float4 vb = *(const float4*)&W[(size_t)(n0b + row) * Kd + q * 4];
            *(uint2*)&Ad[row * GS_AS + q * 2] = make_uint2(h2u(va.x, va.y), h2u(va.z, va.w));
            *(uint2*)&Bd[row * GS_AS + q * 2] = make_uint2(h2u(vb.x, vb.y), h2u(vb.z, vb.w));
        }
    }
    __syncthreads();

    for (int c = 0; c < NC; c++) {
        uint32_t Ab = sb + ((c & 1) ? GS_TILE * 4 : 0);
        uint32_t Bb = sb + 2 * GS_TILE * 4 + ((c & 1) ? GS_TILE * 4 : 0);

        uint2 pah[4], pbh[4];
        if (c + 1 < NC) {
            int kk = (c + 1) * 32;
            #pragma unroll
            for (int i = 0; i < 4; i++) {
                int g = tid + i * 256;
                int row = g >> 3, q = g & 7;
                float4 va = *(const float4*)&A[(size_t)(m0 + row) * Kd + kk + q * 4];
                float4 vb = *(const float4*)&W[(size_t)(n0b + row) * Kd + kk + q * 4];
                pah[i] = make_uint2(h2u(va.x, va.y), h2u(va.z, va.w));
                pbh[i] = make_uint2(h2u(vb.x, vb.y), h2u(vb.z, vb.w));
            }
        }

        #pragma unroll
        for (int ks = 0; ks < 2; ks++) {
            uint4 av[4];
            uint2 bv[4];
            #pragma unroll
            for (int t = 0; t < 4; t++)
                ldmx4(av[t], Ab + (mw * 64 + t * 16 + rowA) * 80 + ks * 32 + kA);
            uint4 b01, b23;
            ldmx4(b01, Bb + (nw * 32 + rowB) * 80 + ks * 32 + kB);
            ldmx4(b23, Bb + (nw * 32 + 16 + rowB) * 80 + ks * 32 + kB);
            bv[0] = make_uint2(b01.x, b01.y); bv[1] = make_uint2(b01.z, b01.w);
            bv[2] = make_uint2(b23.x, b23.y); bv[3] = make_uint2(b23.z, b23.w);
            #pragma unroll
            for (int t = 0; t < 4; t++)
                #pragma unroll
                for (int u = 0; u < 4; u++)
                    mma_f16(acc[t][u], av[t], bv[u]);
        }

        if (c + 1 < NC) {
            __syncthreads();
            uint32_t* Ad = gsm + (((c + 1) & 1) ? GS_TILE : 0);
            uint32_t* Bd = gsm + 2 * GS_TILE + (((c + 1) & 1) ? GS_TILE : 0);
            #pragma unroll
            for (int i = 0; i < 4; i++) {
                int g = tid + i * 256;
                int row = g >> 3, q = g & 7;
                *(uint2*)&Ad[row * GS_AS + q * 2] = pah[i];
                *(uint2*)&Bd[row * GS_AS + q * 2] = pbh[i];
            }
            __syncthreads();
        }
    }

    #pragma unroll
    for (int t = 0; t < 4; t++) {
        int r0 = m0 + mw * 64 + t * 16 + qd;
        #pragma unroll
        for (int u = 0; u < 4; u++) {
            int col = n0b + nw * 32 + u * 8 + pd * 2;
            float v0 = acc[t][u][0], v1 = acc[t][u][1];
            float v2 = acc[t][u][2], v3 = acc[t][u][3];
            if (Ch) {
                *(uint32_t*)&Ch[(size_t)r0 * DM + col] = h2u(v0 * outScale, v1 * outScale);
                *(uint32_t*)&Ch[(size_t)(r0 + 8) * DM + col] = h2u(v2 * outScale, v3 * outScale);
            } else {
                if (sigmoidFlag) {
                    v0 = 1.f / (1.f + __expf(-v0));
                    v1 = 1.f / (1.f + __expf(-v1));
                    v2 = 1.f / (1.f + __expf(-v2));
                    v3 = 1.f / (1.f + __expf(-v3));
                }
                *(float2*)&Cf[(size_t)r0 * DM + col]       = make_float2(v0, v1);
                *(float2*)&Cf[(size_t)(r0 + 8) * DM + col] = make_float2(v2, v3);
            }
        }
    }
}

// ---------------- K+V fused GEMM: half A (pe), half W, ldmatrix fragments ----------
__global__ void __launch_bounds__(256, 2) kvgemm_kernel() {
    extern __shared__ uint32_t gsm[];
    uint32_t sb = smem_u32(gsm);
    int tid = threadIdx.x;
    int lane = tid & 31, wid = tid >> 5;
    int mw = wid & 1, nw = wid >> 1;
    int qd = lane >> 2, pd = lane & 3;
    LANE_FRAG_OFFS(lane);
    int bx = blockIdx.x;
    int n0b = (bx & 1) * 128;
    const __half* A = g_peh;
    const __half* W = (bx >> 1) ? g_Wvh : g_Wkh;
    __half* C = (bx >> 1) ? g_Vh : g_Kh;
    int m0 = blockIdx.y * 128;
    const int NC = 6;

    float acc[4][4][4];
    #pragma unroll
    for (int t = 0; t < 4; t++)
        #pragma unroll
        for (int u = 0; u < 4; u++)
            #pragma unroll
            for (int j = 0; j < 4; j++) acc[t][u][j] = 0.f;

    {
        uint32_t* Ad = gsm;
        uint32_t* Bd = gsm + 2 * GS_TILE;
        #pragma unroll
        for (int i = 0; i < 2; i++) {
            int g = tid + i * 256;
            int row = g >> 2, q = g & 3;
            *(uint4*)&Ad[row * GS_AS + q * 4] =
                *(const uint4*)&A[(size_t)(m0 + row) * D3 + q * 8];
            *(uint4*)&Bd[row * GS_AS + q * 4] =
                *(const uint4*)&W[(size_t)(n0b + row) * D3 + q * 8];
        }
    }
    __syncthreads();

    for (int c = 0; c < NC; c++) {
        uint32_t Ab = sb + ((c & 1) ? GS_TILE * 4 : 0);
        uint32_t Bb = sb + 2 * GS_TILE * 4 + ((c & 1) ? GS_TILE * 4 : 0);

        uint4 pah[2], pbh[2];
        if (c + 1 < NC) {
            int kk = (c + 1) * 32;
            #pragma unroll
            for (int i = 0; i < 2; i++) {
                int g = tid + i * 256;
                int row = g >> 2, q = g & 3;
                pah[i] = *(const uint4*)&A[(size_t)(m0 + row) * D3 + kk + q * 8];
                pbh[i] = *(const uint4*)&W[(size_t)(n0b + row) * D3 + kk + q * 8];
            }
        }

        #pragma unroll
        for (int ks = 0; ks < 2; ks++) {
            uint4 av[4];
            uint2 bv[4];
            #pragma unroll
            for (int t = 0; t < 4; t++)
                ldmx4(av[t], Ab + (mw * 64 + t * 16 + rowA) * 80 + ks * 32 + kA);
            uint4 b01, b23;
            ldmx4(b01, Bb + (nw * 32 + rowB) * 80 + ks * 32 + kB);
            ldmx4(b23, Bb + (nw * 32 + 16 + rowB) * 80 + ks * 32 + kB);
            bv[0] = make_uint2(b01.x, b01.y); bv[1] = make_uint2(b01.z, b01.w);
            bv[2] = make_uint2(b23.x, b23.y); bv[3] = make_uint2(b23.z, b23.w);
            #pragma unroll
            for (int t = 0; t < 4; t++)
                #pragma unroll
                for (int u = 0; u < 4; u++)
                    mma_f16(acc[t][u], av[t], bv[u]);
        }

        if (c + 1 < NC) {
            __syncthreads();
            uint32_t* Ad = gsm + (((c + 1) & 1) ? GS_TILE : 0);
            uint32_t* Bd = gsm + 2 * GS_TILE + (((c + 1) & 1) ? GS_TILE : 0);
            #pragma unroll
            for (int i = 0; i < 2; i++) {
                int g = tid + i * 256;
                int row = g >> 2, q = g & 3;
                *(uint4*)&Ad[row * GS_AS + q * 4] = pah[i];
                *(uint4*)&Bd[row * GS_AS + q * 4] = pbh[i];
            }
            __syncthreads();
        }
    }

    #pragma unroll
    for (int t = 0; t < 4; t++) {
        int r0 = m0 + mw * 64 + t * 16 + qd;
        #pragma unroll
        for (int u = 0; u < 4; u++) {
            int col = n0b + nw * 32 + u * 8 + pd * 2;
            *(uint32_t*)&C[(size_t)r0 * DM + col] = h2u(acc[t][u][0], acc[t][u][1]);
            *(uint32_t*)&C[(size_t)(r0 + 8) * DM + col] = h2u(acc[t][u][2], acc[t][u][3]);
        }
    }
}

// ---------------- fused prep: conv wf + Wk/Wv/Wf halves + pos_sum ------------------
__global__ void prep_kernel(const float* __restrict__ w3, const float* __restrict__ w5,
                            const float* __restrict__ w7, const float* __restrict__ Wk,
                            const float* __restrict__ Wv, const float* __restrict__ Wf,
                            const float* __restrict__ emb) {
    int bid = blockIdx.x;
    int tid = threadIdx.x;
    if (bid < 84) {                        // conv weights fragment-major: 21504 uint2
        int idx = bid * 256 + tid;
        if (idx < 21504) {
            int lane = idx & 31;
            int ks = (idx >> 5) & 3;
            int rem = idx >> 7;            // tp*24 + ct
            int ct = rem % 24;
            int tp = rem / 24;
            int qd = lane >> 2, pd = lane & 3;
            int c = ct * 8 + qd;
            int kw0 = ks * 8 + pd;
            float v[4];
            #pragma unroll
            for (int e = 0; e < 4; e++) {
                int i = (kw0 + (e >> 1) * 4) * 2 + (e & 1);
                float val = 0.f;
                if (c < 64)       { if (tp >= 2 && tp <= 4) val = w3[(c * 64 + i) * 3 + (tp - 2)]; }
                else if (c < 128) { int cc = c - 64; if (tp >= 1 && tp <= 5) val = w5[(cc * 64 + i) * 5 + (tp - 1)]; }
                else              { int cc = c - 128; val = w7[(cc * 64 + i) * 7 + tp]; }
                v[e] = val;
            }
            g_wf[idx] = make_uint2(h2u(v[0], v[1]), h2u(v[2], v[3]));
        }
    } else if (bid < 84 + 640) {           // Wk/Wv/Wf: 163840 halves
        int idx = (bid - 84) * 256 + tid;
        const int NK = DM * D3;
        if (idx < NK) g_Wkh[idx] = __float2half_rn(Wk[idx]);
        else if (idx < 2 * NK) g_Wvh[idx - NK] = __float2half_rn(Wv[idx - NK]);
        else if (idx < 2 * NK + DM * DM) g_Wfh[idx - 2 * NK] = __float2half_rn(Wf[idx - 2 * NK]);
    } else {                               // pos_sum: 512 rows x 192
        int j = bid - (84 + 640);
        int d = tid;
        if (d < D3) {
            float acc = 0.f;
            #pragma unroll
            for (int delta = -29; delta <= 29; delta++) {
                int i = j - delta;
                if (i >= 0 && i < MN) acc += emb[(delta + 30) * D3 + d];
            }
            int cpos = j - 29;
            if (cpos > 0) acc += (float)cpos * emb[60 * D3 + d];
            int cneg = 482 - j;
            if (cneg > 0) acc += (float)cneg * emb[0 * D3 + d];
            g_pos_sum[j * D3 + d] = acc;
        }
    }
}

// ---------------- multi-scale conv: channel-split, coalesced weight frags ----------
#define CXR2 38
#define CXS 36
#define CONV_SMEM (CXR2 * CXS * 4)   // 5472 B

__device__ __forceinline__ constexpr int conv_abase(int tp) {
    return (tp >= 2 && tp <= 4) ? 0 : ((tp == 1 || tp == 5) ? 64 : 128);
}

__global__ void __launch_bounds__(128) conv_kernel(
    const float* __restrict__ xv, const float* __restrict__ b3,
    const float* __restrict__ b5, const float* __restrict__ b7) {
    extern __shared__ uint32_t csm[];
    uint32_t* xvs = csm;
    uint32_t xb = smem_u32(csm);
    int blk = blockIdx.x;              // ((b*16 + sblk) << 1) | chalf
    int ch = blk & 1;
    int sblk = (blk >> 1) & 15;
    int b = blk >> 5;
    int s0 = sblk * 32;
    int cbase = ch * 96;
    int tid = threadIdx.x;
    int lane = tid & 31, nw = tid >> 5;
    int qd = lane >> 2, pd = lane & 3;
    LANE_FRAG_OFFS(lane);
    int ct0 = ch * 12 + nw * 3;        // this warp's first 8-channel tile

    for (int g = tid; g < CXR2 * 16; g += 128) {
        int row = g >> 4, c4 = g & 15;
        int s = s0 - 3 + row;
        float4 v = make_float4(0.f, 0.f, 0.f, 0.f);
        if (s >= 0 && s < MN) v = *(const float4*)&xv[((size_t)b * MN + s) * VD + c4 * 4];
        *(uint2*)&xvs[row * CXS + c4 * 2] = make_uint2(h2u(v.x, v.y), h2u(v.z, v.w));
    }
    __syncthreads();

    float acc[2][3][4];
    #pragma unroll
    for (int t = 0; t < 2; t++)
        #pragma unroll
        for (int u = 0; u < 3; u++)
            #pragma unroll
            for (int j = 0; j < 4; j++) acc[t][u][j] = 0.f;

    uint2 bvb[2][3];
    {
        const int ab0 = conv_abase(0);
        #pragma unroll
        for (int u = 0; u < 3; u++) {
            if ((ct0 + u) * 8 >= ab0)
                bvb[0][u] = __ldg(&g_wf[(((0 * 24 + ct0 + u) * 4 + 0) << 5) + lane]);
        }
    }

    #pragma unroll
    for (int step = 0; step < 28; step++) {
        const int tp = step >> 2, ks = step & 3;
        const int abase = conv_abase(tp);

        if (step + 1 < 28) {
            const int tp2 = (step + 1) >> 2, ks2 = (step + 1) & 3;
            const int ab2 = conv_abase(tp2);
            #pragma unroll
            for (int u = 0; u < 3; u++) {
                if ((ct0 + u) * 8 >= ab2)
                    bvb[(step + 1) & 1][u] =
                        __ldg(&g_wf[(((tp2 * 24 + ct0 + u) * 4 + ks2) << 5) + lane]);
            }
        }

        uint4 av[2];
        #pragma unroll
        for (int t = 0; t < 2; t++)
            ldmx4(av[t], xb + (t * 16 + rowA + tp) * 144 + ks * 32 + kA);
        #pragma unroll
        for (int u = 0; u < 3; u++) {
            if ((ct0 + u) * 8 >= abase) {
                #pragma unroll
                for (int t = 0; t < 2; t++)
                    mma_f16(acc[t][u], av[t], bvb[step & 1][u]);
            }
        }
    }

    #pragma unroll
    for (int t = 0; t < 2; t++) {
        int s = s0 + t * 16 + qd;
        #pragma unroll
        for (int u = 0; u < 3; u++) {
            int col = cbase + nw * 24 + u * 8 + pd * 2;
            float bb0 = col < 64 ? b3[col] : (col < 128 ? b5[col - 64] : b7[col - 128]);
            int c1 = col + 1;
            float bb1 = c1 < 64 ? b3[c1] : (c1 < 128 ? b5[c1 - 64] : b7[c1 - 128]);
            *(uint32_t*)&g_xmh[((size_t)b * MN + s) * D3 + col] =
                h2u(acc[t][u][0] + bb0, acc[t][u][1] + bb1);
            *(uint32_t*)&g_xmh[((size_t)b * MN + s + 8) * D3 + col] =
                h2u(acc[t][u][2] + bb0, acc[t][u][3] + bb1);
        }
    }
}

// ---------------- rel-pos encoding: half2-vectorized -------------------------------
__global__ void pe_kernel(const float* __restrict__ emb,
                          const float* __restrict__ dww, const float* __restrict__ dwb) {
    int idx = blockIdx.x * 256 + threadIdx.x;   // half2 index; total BB*MN*96
    int d2 = idx % 96;
    int r = idx / 96;
    int j = r & (MN - 1);
    int d = d2 * 2;
    const uint32_t* xm2 = (const uint32_t*)g_xmh;
    uint32_t* pe2 = (uint32_t*)g_peh;
    float2 xc = u2f2(xm2[idx]);
    float fC0 = xc.x + emb[30 * D3 + d];
    float fC1 = xc.y + emb[30 * D3 + d + 1];
    float fL0 = 0.f, fL1 = 0.f, fR0 = 0.f, fR1 = 0.f;
    if (j > 0) {
        float2 xl = u2f2(xm2[idx - 96]);
        fL0 = xl.x + emb[29 * D3 + d];
        fL1 = xl.y + emb[29 * D3 + d + 1];
    }
    if (j < MN - 1) {
        float2 xr = u2f2(xm2[idx + 96]);
        fR0 = xr.x + emb[31 * D3 + d];
        fR1 = xr.y + emb[31 * D3 + d + 1];
    }
    float dg0 = fL0 * dww[d * 3 + 0] + fC0 * dww[d * 3 + 1] + fR0 * dww[d * 3 + 2] + dwb[d];
    float dg1 = fL1 * dww[d * 3 + 3] + fC1 * dww[d * 3 + 4] + fR1 * dww[d * 3 + 5] + dwb[d + 1];
    float o0 = xc.x + (g_pos_sum[j * D3 + d] - fC0 + dg0) * (1.0f / (float)MN);
    float o1 = xc.y + (g_pos_sum[j * D3 + d + 1] - fC1 + dg1) * (1.0f / (float)MN);
    pe2[idx] = h2u(o0, o1);
}

// ---------------- attention: two interleaved 16-key blocks per iteration ----------
#define AK_STRIDE 20
#define AV_STRIDE 260
#define ATT_SMEM ((MN * AK_STRIDE + DK * AV_STRIDE) * 4)   // 74240 B

__global__ void __launch_bounds__(256, 2) attn_kernel() {
    extern __shared__ uint32_t ash[];
    uint32_t* Ks = ash;
    uint32_t* VT = ash + MN * AK_STRIDE;
    uint32_t Kb = smem_u32(ash);
    uint32_t Vb = Kb + MN * AK_STRIDE * 4;
    int blk = blockIdx.x;
    int qblk = blk & 3;
    int h = (blk >> 2) & 7;
    int b = blk >> 5;
    int tid = threadIdx.x;
    int lane = tid & 31, wid = tid >> 5;
    int qd = lane >> 2, pd = lane & 3;
    LANE_FRAG_OFFS(lane);
    (void)rowA; (void)kA;

    const __half* Kg = g_Kh + (size_t)b * MN * DM + h * DK;
    for (int i = tid; i < MN * 4; i += 256) {
        int s = i >> 2, c8 = i & 3;
        uint4 kv = *(const uint4*)&Kg[(size_t)s * DM + c8 * 8];
        *(uint4*)&Ks[s * AK_STRIDE + c8 * 4] = kv;
    }
    const __half* Vg = g_Vh + (size_t)b * MN * DM + h * DK;
    for (int g = tid; g < 1024; g += 256) {
        int spair = g >> 2, q = g & 3;
        int s = spair * 2;
        uint4 a = *(const uint4*)&Vg[(size_t)s * DM + q * 8];
        uint4 bq = *(const uint4*)&Vg[(size_t)(s + 1) * DM + q * 8];
        int d0 = q * 8;
        VT[(d0 + 0) * AV_STRIDE + spair] = (a.x & 0xFFFFu) | (bq.x << 16);
        VT[(d0 + 1) * AV_STRIDE + spair] = (a.x >> 16) | (bq.x & 0xFFFF0000u);
        VT[(d0 + 2) * AV_STRIDE + spair] = (a.y & 0xFFFFu) | (bq.y << 16);
        VT[(d0 + 3) * AV_STRIDE + spair] = (a.y >> 16) | (bq.y & 0xFFFF0000u);
        VT[(d0 + 4) * AV_STRIDE + spair] = (a.z & 0xFFFFu) | (bq.z << 16);
        VT[(d0 + 5) * AV_STRIDE + spair] = (a.z >> 16) | (bq.z & 0xFFFF0000u);
        VT[(d0 + 6) * AV_STRIDE + spair] = (a.w & 0xFFFFu) | (bq.w << 16);
        VT[(d0 + 7) * AV_STRIDE + spair] = (a.w >> 16) | (bq.w & 0xFFFF0000u);
    }
    __syncthreads();

    int m0 = qblk * 256 + wid * 32;
    const __half* Qg = g_Qh + ((size_t)b * LL + m0) * DM + h * DK;
    uint4 aq[2][2];
    #pragma unroll
    for (int t = 0; t < 2; t++)
        #pragma unroll
        for (int ks = 0; ks < 2; ks++) {
            int r = t * 16 + qd;
            int c = ks * 16 + pd * 2;
            aq[t][ks].x = *(const uint32_t*)&Qg[(size_t)r * DM + c];
            aq[t][ks].y = *(const uint32_t*)&Qg[(size_t)(r + 8) * DM + c];
            aq[t][ks].z = *(const uint32_t*)&Qg[(size_t)r * DM + c + 8];
            aq[t][ks].w = *(const uint32_t*)&Qg[(size_t)(r + 8) * DM + c + 8];
        }

    float o[2][4][4];
    #pragma unroll
    for (int t = 0; t < 2; t++)
        #pragma unroll
        for (int nv = 0; nv < 4; nv++)
            #pragma unroll
            for (int j = 0; j < 4; j++) o[t][nv][j] = 0.f;
    float rs[2][2] = {{0.f, 0.f}, {0.f, 0.f}};

    for (int s0 = 0; s0 < MN; s0 += 32) {
        int s1 = s0 + 16;

        // ---- block A loads ----
        uint2 bvA[4];
        {
            uint4 m0v, m1v;
            ldmx4(m0v, Vb + rowB * 1040 + s0 * 2 + kB);
            ldmx4(m1v, Vb + (16 + rowB) * 1040 + s0 * 2 + kB);
            bvA[0] = make_uint2(m0v.x, m0v.y); bvA[1] = make_uint2(m0v.z, m0v.w);
            bvA[2] = make_uint2(m1v.x, m1v.y); bvA[3] = make_uint2(m1v.z, m1v.w);
        }
        uint2 bkA[2][2];
        #pragma unroll
        for (int ks = 0; ks < 2; ks++) {
            uint4 m;
            ldmx4(m, Kb + (s0 + rowB) * 80 + ks * 32 + kB);
            bkA[0][ks] = make_uint2(m.x, m.y);
            bkA[1][ks] = make_uint2(m.z, m.w);
        }

        // ---- QK A ----
        float cA[2][2][4];
        #pragma unroll
        for (int t = 0; t < 2; t++)
            #pragma unroll
            for (int n = 0; n < 2; n++) {
                #pragma unroll
                for (int j = 0; j < 4; j++) cA[t][n][j] = 0.f;
                #pragma unroll
                for (int ks = 0; ks < 2; ks++)
                    mma_f16(cA[t][n], aq[t][ks], bkA[n][ks]);
            }

        // ---- block B loads (independent; overlap with exp A below) ----
        uint2 bvB[4];
        {
            uint4 m0v, m1v;
            ldmx4(m0v, Vb + rowB * 1040 + s1 * 2 + kB);
            ldmx4(m1v, Vb + (16 + rowB) * 1040 + s1 * 2 + kB);
            bvB[0] = make_uint2(m0v.x, m0v.y); bvB[1] = make_uint2(m0v.z, m0v.w);
            bvB[2] = make_uint2(m1v.x, m1v.y); bvB[3] = make_uint2(m1v.z, m1v.w);
        }
        uint2 bkB[2][2];
        #pragma unroll
        for (int ks = 0; ks < 2; ks++) {
            uint4 m;
            ldmx4(m, Kb + (s1 + rowB) * 80 + ks * 32 + kB);
            bkB[0][ks] = make_uint2(m.x, m.y);
            bkB[1][ks] = make_uint2(m.z, m.w);
        }

        // ---- QK B (mma pipe busy while exp A's MUFU drains) ----
        float cB[2][2][4];
        #pragma unroll
        for (int t = 0; t < 2; t++)
            #pragma unroll
            for (int n = 0; n < 2; n++) {
                #pragma unroll
                for (int j = 0; j < 4; j++) cB[t][n][j] = 0.f;
                #pragma unroll
                for (int ks = 0; ks < 2; ks++)
                    mma_f16(cB[t][n], aq[t][ks], bkB[n][ks]);
            }

        // ---- exp A + PV A ----
        #pragma unroll
        for (int t = 0; t < 2; t++) {
            uint32_t p0 = ex2h2(f22h2(cA[t][0][0], cA[t][0][1]));
            uint32_t p1 = ex2h2(f22h2(cA[t][0][2], cA[t][0][3]));
            uint32_t p2 = ex2h2(f22h2(cA[t][1][0], cA[t][1][1]));
            uint32_t p3 = ex2h2(f22h2(cA[t][1][2], cA[t][1][3]));
            uint4 ap = make_uint4(p0, p1, p2, p3);
            __half2 sh0 = __hadd2(*(__half2*)&p0, *(__half2*)&p2);
            __half2 sh1 = __hadd2(*(__half2*)&p1, *(__half2*)&p3);
            float2 f0 = __half22float2(sh0);
            float2 f1 = __half22float2(sh1);
            rs[t][0] += f0.x + f0.y;
            rs[t][1] += f1.x + f1.y;
            #pragma unroll
            for (int nv = 0; nv < 4; nv++)
                mma_f16(o[t][nv], ap, bvA[nv]);
        }

        // ---- exp B + PV B ----
        #pragma unroll
        for (int t = 0; t < 2; t++) {
            uint32_t p0 = ex2h2(f22h2(cB[t][0][0], cB[t][0][1]));
            uint32_t p1 = ex2h2(f22h2(cB[t][0][2], cB[t][0][3]));
            uint32_t p2 = ex2h2(f22h2(cB[t][1][0], cB[t][1][1]));
            uint32_t p3 = ex2h2(f22h2(cB[t][1][2], cB[t][1][3]));
            uint4 ap = make_uint4(p0, p1, p2, p3);
            __half2 sh0 = __hadd2(*(__half2*)&p0, *(__half2*)&p2);
            __half2 sh1 = __hadd2(*(__half2*)&p1, *(__half2*)&p3);
            float2 f0 = __half22float2(sh0);
            float2 f1 = __half22float2(sh1);
            rs[t][0] += f0.x + f0.y;
            rs[t][1] += f1.x + f1.y;
            #pragma unroll
            for (int nv = 0; nv < 4; nv++)
                mma_f16(o[t][nv], ap, bvB[nv]);
        }
    }

    __half* Ah = g_attnh;
    #pragma unroll
    for (int t = 0; t < 2; t++) {
        #pragma unroll
        for (int r = 0; r < 2; r++) {
            rs[t][r] += __shfl_xor_sync(0xFFFFFFFFu, rs[t][r], 1);
            rs[t][r] += __shfl_xor_sync(0xFFFFFFFFu, rs[t][r], 2);
        }
        float inv0 = 1.f / rs[t][0];
        float inv1 = 1.f / rs[t][1];
        int r0 = m0 + t * 16 + qd;
        #pragma unroll
        for (int nv = 0; nv < 4; nv++) {
            int col = h * DK + nv * 8 + pd * 2;
            *(uint32_t*)&Ah[((size_t)b * LL + r0) * DM + col] =
                h2u(o[t][nv][0] * inv0, o[t][nv][1] * inv0);
            *(uint32_t*)&Ah[((size_t)b * LL + r0 + 8) * DM + col] =
                h2u(o[t][nv][2] * inv1, o[t][nv][3] * inv1);
        }
    }
}

// ---------------- fc GEMM fused with gate + residual + LayerNorm ------------------
#define FA_TILE (64 * GS_AS)
#define FB_TILE (256 * GS_AS)
#define FSM_BYTES ((2 * FA_TILE + 2 * FB_TILE + 512) * 4)   // 53248 B

__global__ void __launch_bounds__(256, 2) fcln_kernel(
    const float* __restrict__ fb, const float* __restrict__ xs,
    const float* __restrict__ lnw, const float* __restrict__ lnb,
    float* __restrict__ out) {
    extern __shared__ uint32_t fsm[];
    uint32_t sb = smem_u32(fsm);
    float* red = (float*)(fsm + 2 * FA_TILE + 2 * FB_TILE);
    const __half* A = g_attnh;
    const __half* Wf = g_Wfh;
    int tid = threadIdx.x;
    int lane = tid & 31, wid = tid >> 5;
    int mw = wid & 1, nw = wid >> 1;
    int qd = lane >> 2, pd = lane & 3;
    LANE_FRAG_OFFS(lane);
    int row0 = blockIdx.x * 64;
    int b = row0 >> 10;
    const int NC = 8;

    float acc[2][8][4];
    #pragma unroll
    for (int t = 0; t < 2; t++)
        #pragma unroll
        for (int u = 0; u < 8; u++)
            #pragma unroll
            for (int j = 0; j < 4; j++) acc[t][u][j] = 0.f;

    {
        uint32_t* Ad = fsm;
        uint32_t* Bd = fsm + 2 * FA_TILE;
        #pragma unroll
        for (int i = 0; i < 5; i++) {
            int g = tid + i * 256;
            if (g < 256) {
                int row = g >> 2, q = g & 3;
                *(uint4*)&Ad[row * GS_AS + q * 4] =
                    *(const uint4*)&A[(size_t)(row0 + row) * DM + q * 8];
            } else {
                int j = g - 256;
                int row = j >> 2, q = j & 3;
                *(uint4*)&Bd[row * GS_AS + q * 4] =
                    *(const uint4*)&Wf[(size_t)row * DM + q * 8];
            }
        }
    }
    __syncthreads();

    for (int c = 0; c < NC; c++) {
        uint32_t Ab = sb + ((c & 1) ? FA_TILE * 4 : 0);
        uint32_t Bb = sb + 2 * FA_TILE * 4 + ((c & 1) ? FB_TILE * 4 : 0);

        uint4 pf[5];
        if (c + 1 < NC) {
            int kk = (c + 1) * 32;
            #pragma unroll
            for (int i = 0; i < 5; i++) {
                int g = tid + i * 256;
                if (g < 256) {
                    int row = g >> 2, q = g & 3;
                    pf[i] = *(const uint4*)&A[(size_t)(row0 + row) * DM + kk + q * 8];
                } else {
                    int j = g - 256;
                    int row = j >> 2, q = j & 3;
                    pf[i] = *(const uint4*)&Wf[(size_t)row * DM + kk + q * 8];
                }
            }
        }

        #pragma unroll
        for (int ks = 0; ks < 2; ks++) {
            uint4 av[2];
            uint2 bv[8];
            #pragma unroll
            for (int t = 0; t < 2; t++)
                ldmx4(av[t], Ab + (mw * 32 + t * 16 + rowA) * 80 + ks * 32 + kA);
            #pragma unroll
            for (int u2 = 0; u2 < 4; u2++) {
                uint4 m;
                ldmx4(m, Bb + (nw * 64 + u2 * 16 + rowB) * 80 + ks * 32 + kB);
                bv[u2 * 2] = make_uint2(m.x, m.y);
                bv[u2 * 2 + 1] = make_uint2(m.z, m.w);
            }
            #pragma unroll
            for (int t = 0; t < 2; t++)
                #pragma unroll
                for (int u = 0; u < 8; u++)
                    mma_f16(acc[t][u], av[t], bv[u]);
        }

        if (c + 1 < NC) {
            __syncthreads();
            uint32_t* Ad = fsm + (((c + 1) & 1) ? FA_TILE : 0);
            uint32_t* Bd = fsm + 2 * FA_TILE + (((c + 1) & 1) ? FB_TILE : 0);
            #pragma unroll
            for (int i = 0; i < 5; i++) {
                int g = tid + i * 256;
                if (g < 256) {
                    int row = g >> 2, q = g & 3;
                    *(uint4*)&Ad[row * GS_AS + q * 4] = pf[i];
                } else {
                    int j = g - 256;
                    int row = j >> 2, q = j & 3;
                    *(uint4*)&Bd[row * GS_AS + q * 4] = pf[i];
                }
            }
            __syncthreads();
        }
    }

    __syncthreads();
    #pragma unroll
    for (int t = 0; t < 2; t++) {
        #pragma unroll
        for (int hf = 0; hf < 2; hf++) {
            int lr = mw * 32 + t * 16 + qd + hf * 8;
            int r = row0 + lr;
            int l = r & 1023;
            const float* gam = g_gamma + ((size_t)b * MN + (l & (MN - 1))) * DM;
            const float* xr = xs + (size_t)r * DM;
            float s1 = 0.f, s2 = 0.f;
            #pragma unroll
            for (int u = 0; u < 8; u++) {
                int col = nw * 64 + u * 8 + pd * 2;
                int j0 = hf * 2;
                float v0 = xr[col] + gam[col] * (acc[t][u][j0] + fb[col]);
                float v1 = xr[col + 1] + gam[col + 1] * (acc[t][u][j0 + 1] + fb[col + 1]);
                acc[t][u][j0] = v0;
                acc[t][u][j0 + 1] = v1;
                s1 += v0 + v1;
                s2 += v0 * v0 + v1 * v1;
            }
            s1 += __shfl_xor_sync(0xFFFFFFFFu, s1, 1);
            s1 += __shfl_xor_sync(0xFFFFFFFFu, s1, 2);
            s2 += __shfl_xor_sync(0xFFFFFFFFu, s2, 1);
            s2 += __shfl_xor_sync(0xFFFFFFFFu, s2, 2);
            if (pd == 0) {
                red[nw * 64 + lr] = s1;
                red[256 + nw * 64 + lr] = s2;
            }
        }
    }
    __syncthreads();
    #pragma unroll
    for (int t = 0; t < 2; t++) {
        #pragma unroll
        for (int hf = 0; hf < 2; hf++) {
            int lr = mw * 32 + t * 16 + qd + hf * 8;
            int r = row0 + lr;
            float t1 = red[lr] + red[64 + lr] + red[128 + lr] + red[192 + lr];
            float t2 = red[256 + lr] + red[320 + lr] + red[384 + lr] + red[448 + lr];
            float mu = t1 * (1.f / 256.f);
            float var = t2 * (1.f / 256.f) - mu * mu;
            float rstd = rsqrtf(var + 1e-5f);
            #pragma unroll
            for (int u = 0; u < 8; u++) {
                int col = nw * 64 + u * 8 + pd * 2;
                int j0 = hf * 2;
                float v0 = (acc[t][u][j0] - mu) * rstd * lnw[col] + lnb[col];
                float v1 = (acc[t][u][j0 + 1] - mu) * rstd * lnw[col + 1] + lnb[col + 1];
                *(float2*)&out[(size_t)r * DM + col] = make_float2(v0, v1);
            }
        }
    }
}

// ---------------- launch: round-14 ordering (prep, then fork Q+Gamma) --------------
extern "C" void kernel_launch(void* const* d_in, const int* in_sizes, int n_in,
                              void* d_out, int out_size) {
    const float* x_spatial  = (const float*)d_in[0];
    const float* x_velocity = (const float*)d_in[1];
    const float* Wg    = (const float*)d_in[2];
    const float* ms_w3 = (const float*)d_in[3];
    const float* ms_b3 = (const float*)d_in[4];
    const float* ms_w5 = (const float*)d_in[5];
    const float* ms_b5 = (const float*)d_in[6];
    const float* ms_w7 = (const float*)d_in[7];
    const float* ms_b7 = (const float*)d_in[8];
    const float* rel_emb = (const float*)d_in[9];
    const float* dw_w  = (const float*)d_in[10];
    const float* dw_b  = (const float*)d_in[11];
    const float* Wq    = (const float*)d_in[12];
    const float* Wk    = (const float*)d_in[13];
    const float* Wv    = (const float*)d_in[14];
    const float* fc_w  = (const float*)d_in[15];
    const float* fc_b  = (const float*)d_in[16];
    const float* ln_w  = (const float*)d_in[17];
    const float* ln_b  = (const float*)d_in[18];
    float* out = (float*)d_out;

    float *p_gamma;
    __half *p_Qh;
    cudaGetSymbolAddress((void**)&p_gamma, g_gamma);
    cudaGetSymbolAddress((void**)&p_Qh,    g_Qh);

    cudaFuncSetAttribute(conv_kernel,   cudaFuncAttributeMaxDynamicSharedMemorySize, CONV_SMEM);
    cudaFuncSetAttribute(attn_kernel,   cudaFuncAttributeMaxDynamicSharedMemorySize, ATT_SMEM);
    cudaFuncSetAttribute(mgemm_kernel,  cudaFuncAttributeMaxDynamicSharedMemorySize, GSM_BYTES);
    cudaFuncSetAttribute(kvgemm_kernel, cudaFuncAttributeMaxDynamicSharedMemorySize, GSM_BYTES);
    cudaFuncSetAttribute(fcln_kernel,   cudaFuncAttributeMaxDynamicSharedMemorySize, FSM_BYTES);

    static cudaStream_t s_side = nullptr;
    static cudaEvent_t ev_fork = nullptr, ev_join = nullptr;
    if (s_side == nullptr) {
        cudaStreamCreateWithFlags(&s_side, cudaStreamNonBlocking);
        cudaEventCreateWithFlags(&ev_fork, cudaEventDisableTiming);
        cudaEventCreateWithFlags(&ev_join, cudaEventDisableTiming);
    }

    const float qsc = 0.17677669529663687f * 1.4426950408889634f;   // log2e/sqrt(dk)

    prep_kernel<<<84 + 640 + 512, 256>>>(ms_w3, ms_w5, ms_w7, Wk, Wv, fc_w, rel_emb);

    // fork: Q projection + Gamma on side stream
    cudaEventRecord(ev_fork, 0);
    cudaStreamWaitEvent(s_side, ev_fork, 0);
    mgemm_kernel<<<dim3(2, BB * LL / 128), 256, GSM_BYTES, s_side>>>(
        x_spatial, Wq, nullptr, p_Qh, SD, 0, qsc);
    mgemm_kernel<<<dim3(2, BB * MN / 128), 256, GSM_BYTES, s_side>>>(
        x_velocity, Wg, p_gamma, nullptr, VD, 1, 1.f);
    cudaEventRecord(ev_join, s_side);

    // main chain: conv (channel-split, coalesced weights) -> pe -> K+V
    conv_kernel<<<BB * 16 * 2, 128, CONV_SMEM>>>(x_velocity, ms_b3, ms_b5, ms_b7);
    pe_kernel<<<BB * MN * 96 / 256, 256>>>(rel_emb, dw_w, dw_b);
    kvgemm_kernel<<<dim3(4, BB * MN / 128), 256, GSM_BYTES>>>();

    cudaStreamWaitEvent(0, ev_join, 0);
    attn_kernel<<<BB * NH * 4, 256, ATT_SMEM>>>();
    fcln_kernel<<<BB * LL / 64, 256, FSM_BYTES>>>(fc_b, x_spatial, ln_w, ln_b, out);
}